// round 13
// baseline (speedup 1.0000x reference)
#include <cuda_runtime.h>
#include <math.h>
#include <stdint.h>

#define NN 10000
#define EE 160000
#define FF 256
#define RR 20
#define TE 64
#define CHUNK 2048
#define NCHUNK 79   // ceil(EE / CHUNK)

// ---------------- device scratch ----------------
__device__ float g_P0[NN * FF];
__device__ float g_P1[NN * FF];
__device__ float g_sum[NN * FF];
__device__ float g_sumsq[NN * FF];
__device__ float g_minb[NN * FF];
__device__ float g_maxb[NN * FF];
__device__ float g_deg[NN];
__device__ float g_avglog;
__device__ float g_cat[NN * 3328];
// sort scratch
__device__ int g_chunkCnt[NCHUNK * NN];
__device__ int g_binCnt[NN];
__device__ int g_binBase[NN];
__device__ int g_perm[EE];
__device__ int g_ssrc[EE];
__device__ int g_sdst[EE];
// tf32-rounded weight copies.
// K=256 streamed weights are PACKED per 16-row K-tile: tile t occupies 4096
// floats: [pg in 0..8)][n in 0..256)][hi in 0..2) with pg=(ks>>1)+c pairing
// rows (ks+c, ks+c+4) -- exactly the m16n8k8 B-fragment pair, so one LDS.64
// fetches both b0,b1.
__device__ float g_Wemb[RR * FF];
__device__ float g_Wpre2[FF * FF];
__device__ float g_Ws1[FF * FF];
__device__ float g_Ws2[FF * 3 * FF];     // 3 chunks of 16 packed tiles
__device__ float g_Wlin[RR * 3 * FF];
__device__ float g_Wpost[3328 * FF];     // 208 packed tiles

// ---------------- helpers ----------------
__device__ __forceinline__ float tf32r(float x) {
    uint32_t u;
    asm("cvt.rna.tf32.f32 %0, %1;" : "=r"(u) : "f"(x));
    return __uint_as_float(u);
}
__device__ __forceinline__ uint32_t F2U(float f) { return __float_as_uint(f); }

__device__ __forceinline__ void mma8(float c[4], uint32_t a0, uint32_t a1, uint32_t a2,
                                     uint32_t a3, uint32_t b0, uint32_t b1) {
    asm volatile(
        "mma.sync.aligned.m16n8k8.row.col.f32.tf32.tf32.f32 "
        "{%0,%1,%2,%3},{%4,%5,%6,%7},{%8,%9},{%0,%1,%2,%3};"
        : "+f"(c[0]), "+f"(c[1]), "+f"(c[2]), "+f"(c[3])
        : "r"(a0), "r"(a1), "r"(a2), "r"(a3), "r"(b0), "r"(b1));
}

__device__ __forceinline__ void cp16(uint32_t saddr, const void* g) {
    asm volatile("cp.async.ca.shared.global [%0], [%1], 16;" :: "r"(saddr), "l"(g));
}
__device__ __forceinline__ void cp_commit() { asm volatile("cp.async.commit_group;"); }
__device__ __forceinline__ void cp_wait1()  { asm volatile("cp.async.wait_group 1;"); }
__device__ __forceinline__ void cp_wait0()  { asm volatile("cp.async.wait_group 0;"); }

__device__ __forceinline__ void atomicMaxF(float* p, float v) {
    if (v >= 0.f) atomicMax((int*)p, __float_as_int(v));
    else          atomicMin((unsigned int*)p, __float_as_uint(v));
}
__device__ __forceinline__ void atomicMinF(float* p, float v) {
    if (v >= 0.f) atomicMin((int*)p, __float_as_int(v));
    else          atomicMax((unsigned int*)p, __float_as_uint(v));
}

// map packed index (pg, hi) -> source k-row within 16-row tile
__device__ __forceinline__ int unpack_kr(int pg, int hi) {
    return ((pg >= 4) ? 8 : 0) + (pg & 3) + hi * 4;
}

// ---------------- weight conversion (packs K=256 weights) ----------------
__global__ void cvt_kernel(const float* __restrict__ Wemb, const float* __restrict__ Wpre,
                           const float* __restrict__ Ws1, const float* __restrict__ Ws2,
                           const float* __restrict__ Wlin, const float* __restrict__ Wpost) {
    int i = blockIdx.x * 256 + threadIdx.x;
    if (i < RR * FF)     g_Wemb[i] = tf32r(Wemb[i]);
    if (i < RR * 3 * FF) g_Wlin[i] = tf32r(Wlin[i]);
    if (i < FF * FF) {
        int t = i >> 12, rem = i & 4095, pg = rem >> 9, r2 = rem & 511;
        int n = r2 >> 1, hi = r2 & 1;
        int k = t * 16 + unpack_kr(pg, hi);
        g_Wpre2[i] = tf32r(Wpre[2 * FF * FF + k * 256 + n]);
        g_Ws1[i]   = tf32r(Ws1[k * 256 + n]);
    }
    if (i < FF * 3 * FF) {
        int ch = i / 65536, rem1 = i - ch * 65536;
        int t = rem1 >> 12, rem = rem1 & 4095, pg = rem >> 9, r2 = rem & 511;
        int n = r2 >> 1, hi = r2 & 1;
        int k = t * 16 + unpack_kr(pg, hi);
        g_Ws2[i] = tf32r(Ws2[k * 768 + ch * 256 + n]);
    }
    if (i < 3328 * FF) {
        int t = i >> 12, rem = i & 4095, pg = rem >> 9, r2 = rem & 511;
        int n = r2 >> 1, hi = r2 & 1;
        int k = t * 16 + unpack_kr(pg, hi);
        g_Wpost[i] = tf32r(Wpost[k * 256 + n]);
    }
}

// ---------------- init ----------------
__global__ void init_kernel(const float* __restrict__ x) {
    int i = blockIdx.x * 256 + threadIdx.x;
    if (i < NN * FF) {
        g_sum[i]   = 0.f;
        g_sumsq[i] = 0.f;
        g_minb[i]  = __int_as_float(0x7f800000);
        g_maxb[i]  = __int_as_float(0xff800000);
        int n = i >> 8, c = i & 255;
        g_cat[n * 3328 + c] = tf32r(x[i]);
    }
}

// ---------------- sort: per-chunk histogram (2048-edge chunks) ----------------
__global__ __launch_bounds__(256) void hist_kernel(const int* __restrict__ eidx) {
    __shared__ int shist[NN];
    int b = blockIdx.x, t = threadIdx.x;
    for (int i = t; i < NN; i += 256) shist[i] = 0;
    __syncthreads();
    int ebase = b * CHUNK;
#pragma unroll
    for (int j = 0; j < CHUNK / 256; j++) {
        int e = ebase + j * 256 + t;
        if (e < EE) atomicAdd(&shist[eidx[EE + e]], 1);
    }
    __syncthreads();
    for (int i = t; i < NN; i += 256) g_chunkCnt[b * NN + i] = shist[i];
}

// ---------------- sort: per-bin scan over chunks ----------------
__global__ void scanA_kernel() {
    int d = blockIdx.x * 256 + threadIdx.x;
    if (d >= NN) return;
    int run = 0;
    for (int b = 0; b < NCHUNK; b++) {
        int idx = b * NN + d;
        int t = g_chunkCnt[idx];
        g_chunkCnt[idx] = run;
        run += t;
    }
    g_binCnt[d] = run;
    g_deg[d] = (float)run;
}

// ---------------- sort: exclusive scan over bins (single block) ----------------
__global__ void scanB_kernel() {
    __shared__ int sp[256];
    int t = threadIdx.x;
    int lo = t * 40, hi = min(lo + 40, NN);
    int s = 0;
    for (int i = lo; i < hi; i++) s += g_binCnt[i];
    sp[t] = s;
    __syncthreads();
    for (int off = 1; off < 256; off <<= 1) {
        int v = (t >= off) ? sp[t - off] : 0;
        __syncthreads();
        sp[t] += v;
        __syncthreads();
    }
    int base = (t > 0) ? sp[t - 1] : 0;
    for (int i = lo; i < hi; i++) {
        int c = g_binCnt[i];
        g_binBase[i] = base;
        base += c;
    }
}

// ---------------- sort: stable scatter (8 rounds of 256 per chunk) ----------------
__global__ __launch_bounds__(256) void scatter_kernel(const int* __restrict__ eidx) {
    __shared__ int rc[NN];
    __shared__ int sd[256];
    int b = blockIdx.x, t = threadIdx.x;
    for (int i = t; i < NN; i += 256) rc[i] = 0;
    __syncthreads();
    int ebase = b * CHUNK;
#pragma unroll
    for (int j = 0; j < CHUNK / 256; j++) {
        int e = ebase + j * 256 + t;
        int d = (e < EE) ? eidx[EE + e] : -1;
        sd[t] = d;
        __syncthreads();
        if (d >= 0) {
            int rank = 0;
            for (int k = 0; k < t; k++) rank += (sd[k] == d);
            int pos = g_binBase[d] + g_chunkCnt[b * NN + d] + rc[d] + rank;
            g_perm[pos] = e;
            g_ssrc[pos] = eidx[e];
            g_sdst[pos] = d;
        }
        __syncthreads();
        if (d >= 0) atomicAdd(&rc[d], 1);
        __syncthreads();
    }
}

// ---------------- node precompute: P0/P1 (fp32 scalar) ----------------
__global__ __launch_bounds__(256) void gemm_pre_kernel(const float* __restrict__ x,
                                                       const float* __restrict__ Wpre) {
    __shared__ float sA[64 * 16];
    __shared__ float sW[16 * 256];
    const float* W = Wpre + blockIdx.y * FF * FF;
    float* P = blockIdx.y ? g_P1 : g_P0;
    int tid = threadIdx.x, ty = tid >> 5, tx = tid & 31;
    int n0 = blockIdx.x * 64;
    float acc[8][8];
#pragma unroll
    for (int i = 0; i < 8; i++)
#pragma unroll
        for (int j = 0; j < 8; j++) acc[i][j] = 0.f;

    for (int k0 = 0; k0 < FF; k0 += 16) {
        {
            int vrow = tid >> 2, c4 = tid & 3;
            int n = n0 + vrow;
            float4 av = make_float4(0.f, 0.f, 0.f, 0.f);
            if (n < NN) av = *(const float4*)&x[n * FF + k0 + c4 * 4];
            *(float4*)&sA[vrow * 16 + c4 * 4] = av;
        }
#pragma unroll
        for (int qq = 0; qq < 4; qq++) {
            int v = qq * 256 + tid, row = v >> 6, c4 = v & 63;
            *(float4*)&sW[row * 256 + c4 * 4] = *(const float4*)&W[(k0 + row) * FF + c4 * 4];
        }
        __syncthreads();
#pragma unroll
        for (int kk4 = 0; kk4 < 4; kk4++) {
            float4 a4[8];
#pragma unroll
            for (int i = 0; i < 8; i++) a4[i] = *(const float4*)&sA[(ty * 8 + i) * 16 + kk4 * 4];
#pragma unroll
            for (int u = 0; u < 4; u++) {
                const float* wr = &sW[(kk4 * 4 + u) * 256 + tx * 8];
                float4 b0 = *(const float4*)wr, b1 = *(const float4*)(wr + 4);
                float bb[8] = {b0.x, b0.y, b0.z, b0.w, b1.x, b1.y, b1.z, b1.w};
#pragma unroll
                for (int i = 0; i < 8; i++) {
                    float a = (u == 0) ? a4[i].x : (u == 1) ? a4[i].y : (u == 2) ? a4[i].z : a4[i].w;
#pragma unroll
                    for (int j = 0; j < 8; j++) acc[i][j] = fmaf(a, bb[j], acc[i][j]);
                }
            }
        }
        __syncthreads();
    }
#pragma unroll
    for (int i = 0; i < 8; i++) {
        int n = n0 + ty * 8 + i;
        if (n < NN) {
#pragma unroll
            for (int j = 0; j < 8; j++) P[n * FF + tx * 8 + j] = acc[i][j];
        }
    }
}

// ---------------- tf32 mma building blocks (warp 32x64, 8 warps) ----------------
// B tile in smem is PACKED: 8 pair-rows x 528 floats (264 float2 columns).
// One float2 load yields (b0, b1) for rows (ks+c, ks+c+4).
__device__ __forceinline__ void compute_k16(const float* sA, int astr, int arow0, int k0,
                                            const float* sWb, int lane, int col0,
                                            float acc[2][8][4]) {
    int q = lane >> 2, c = lane & 3;
#pragma unroll
    for (int ks = 0; ks < 16; ks += 8) {
        uint32_t a[2][4];
#pragma unroll
        for (int mt = 0; mt < 2; mt++) {
            const float* ap = sA + (arow0 + mt * 16 + q) * astr + k0 + ks + c;
            a[mt][0] = F2U(ap[0]);
            a[mt][2] = F2U(ap[4]);
            a[mt][1] = F2U(ap[8 * astr]);
            a[mt][3] = F2U(ap[8 * astr + 4]);
        }
        int pg = (ks >> 1) + c;  // ks=0 -> c, ks=8 -> 4+c
        const float2* brow = (const float2*)(sWb + pg * 528) + col0 + q;
#pragma unroll
        for (int nt = 0; nt < 8; nt++) {
            float2 b = brow[nt * 8];
            uint32_t b0 = F2U(b.x);
            uint32_t b1 = F2U(b.y);
            mma8(acc[0][nt], a[0][0], a[0][1], a[0][2], a[0][3], b0, b1);
            mma8(acc[1][nt], a[1][0], a[1][1], a[1][2], a[1][3], b0, b1);
        }
    }
}

// Full K=256 GEMM; Wg points to PACKED tiles (4096 floats each, contiguous).
__device__ __forceinline__ void mma_loop(const float* sA, int astr, float* sW, uint32_t sWu,
                                         const float* __restrict__ Wg,
                                         int tid, int lane, int arow0, int col0,
                                         float acc[2][8][4]) {
#pragma unroll
    for (int mt = 0; mt < 2; mt++)
#pragma unroll
        for (int nt = 0; nt < 8; nt++)
#pragma unroll
            for (int z = 0; z < 4; z++) acc[mt][nt][z] = 0.f;
    {
#pragma unroll
        for (int qq = 0; qq < 4; qq++) {
            int v = qq * 256 + tid, r8 = v >> 7, c4 = (v & 127) * 4;
            cp16(sWu + (uint32_t)((r8 * 528 + c4) * 4), Wg + v * 4);
        }
        cp_commit();
    }
    for (int t = 0; t < 16; t++) {
        if (t + 1 < 16) {
            const float* src = Wg + (t + 1) * 4096;
            uint32_t dbase = sWu + (uint32_t)((((t + 1) & 1) * 4224) * 4);
#pragma unroll
            for (int qq = 0; qq < 4; qq++) {
                int v = qq * 256 + tid, r8 = v >> 7, c4 = (v & 127) * 4;
                cp16(dbase + (uint32_t)((r8 * 528 + c4) * 4), src + v * 4);
            }
            cp_commit();
            cp_wait1();
        } else {
            cp_wait0();
        }
        __syncthreads();
        compute_k16(sA, astr, arow0, t * 16, sW + (t & 1) * 4224, lane, col0, acc);
        __syncthreads();
    }
}

// K=24 (zero-padded K=20) mma: A = sRbfA (stride 28), B = sW rows 0..23 (UNPACKED, stride 264).
__device__ __forceinline__ void fmma24(const float* sRbfA, const float* sW, int lane,
                                       int arow0, int col0, float facc[2][8][4]) {
#pragma unroll
    for (int mt = 0; mt < 2; mt++)
#pragma unroll
        for (int nt = 0; nt < 8; nt++)
#pragma unroll
            for (int z = 0; z < 4; z++) facc[mt][nt][z] = 0.f;
    int q = lane >> 2, c = lane & 3;
#pragma unroll
    for (int ks = 0; ks < 24; ks += 8) {
        uint32_t a[2][4];
#pragma unroll
        for (int mt = 0; mt < 2; mt++) {
            const float* ap = sRbfA + (arow0 + mt * 16 + q) * 28 + ks + c;
            a[mt][0] = F2U(ap[0]);
            a[mt][2] = F2U(ap[4]);
            a[mt][1] = F2U(ap[8 * 28]);
            a[mt][3] = F2U(ap[8 * 28 + 4]);
        }
#pragma unroll
        for (int nt = 0; nt < 8; nt++) {
            const float* bp = sW + (ks + c) * 264 + col0 + nt * 8 + q;
            uint32_t b0 = F2U(bp[0]);
            uint32_t b1 = F2U(bp[4 * 264]);
            mma8(facc[0][nt], a[0][0], a[0][1], a[0][2], a[0][3], b0, b1);
            mma8(facc[1][nt], a[1][0], a[1][1], a[1][2], a[1][3], b0, b1);
        }
    }
}

// ---------------- fused edge kernel (256 threads; sorted edges; segmented epilogues) ----------------
// smem floats: sA 64x260 | sM 64x260 | sW 2x4224 | sRbfA 64x28 | sEv 192 | src/dst/perm 192 ints
#define EDGE_SMEM_FLOATS (16640 + 16640 + 8448 + 1792 + 192 + 192)
#define EDGE_SMEM_BYTES (EDGE_SMEM_FLOATS * 4)

__global__ __launch_bounds__(256, 1) void edge_kernel(
    const float* __restrict__ x, const float* __restrict__ edge_rbf,
    const float* __restrict__ edge_vec,
    const float* __restrict__ bemb, const float* __restrict__ bpre,
    const float* __restrict__ bs1, const float* __restrict__ bs2,
    float* __restrict__ out_v) {
    extern __shared__ float sm[];
    float* sA    = sm;
    float* sM    = sm + 16640;
    float* sW    = sm + 33280;
    float* sRbfA = sm + 41728;
    float* sEv   = sm + 43520;
    int* sSrc  = (int*)(sm + 43712);
    int* sDst  = sSrc + 64;
    int* sPerm = sDst + 64;
    uint32_t sWu = (uint32_t)__cvta_generic_to_shared(sW);

    int tid = threadIdx.x, lane = tid & 31, w = tid >> 5;
    int arow0 = (w & 1) * 32, col0 = (w >> 1) * 64;
    int q = lane >> 2, cc = lane & 3;
    int e0 = blockIdx.x * TE;

    if (tid < TE) {
        sSrc[tid]  = g_ssrc[e0 + tid];
        sDst[tid]  = g_sdst[e0 + tid];
        sPerm[tid] = g_perm[e0 + tid];
    }
    __syncthreads();

    // rbf gather (via perm), tf32-rounded, padded to 24 cols (stride 28)
#pragma unroll
    for (int j = 0; j < 5; j++) {
        int i = tid + j * 256;
        int e = i / 20, k = i - e * 20;
        sRbfA[e * 28 + k] = tf32r(edge_rbf[(size_t)sPerm[e] * RR + k]);
    }
    { int e = tid >> 2, k = 20 + (tid & 3); sRbfA[e * 28 + k] = 0.f; }
    if (tid < 192) {
        int e = tid / 3, comp = tid - e * 3;
        sEv[tid] = edge_vec[(size_t)sPerm[e] * 3 + comp];
    }
    // Wemb -> sW rows 0..19 (stride 264), zero rows 20..23
#pragma unroll
    for (int j = 0; j < 5; j++) {
        int v = tid + j * 256, row = v >> 6, c4 = (v & 63) * 4;
        *(float4*)&sW[row * 264 + c4] = *(const float4*)&g_Wemb[row * 256 + c4];
    }
    { int row = 20 + (tid >> 6), c4 = (tid & 63) * 4;
      *(float4*)&sW[row * 264 + c4] = make_float4(0.f, 0.f, 0.f, 0.f); }
    __syncthreads();

    // prefill sM = P0[src] + P1[dst] + bpre (4096 float4s)
#pragma unroll
    for (int j = 0; j < 16; j++) {
        int f = (tid + j * 256) * 4;
        int r = f >> 8, c = f & 255;
        int s = sSrc[r], d = sDst[r];
        float4 p0 = *(const float4*)&g_P0[s * 256 + c];
        float4 p1 = *(const float4*)&g_P1[d * 256 + c];
        float4 bb = *(const float4*)&bpre[c];
        *(float4*)&sM[r * 260 + c] =
            make_float4(p0.x + p1.x + bb.x, p0.y + p1.y + bb.y,
                        p0.z + p1.z + bb.z, p0.w + p1.w + bb.w);
    }

    float acc[2][8][4];

    // ---- stage 1: sA = round(relu(rbf@Wemb + bemb)) ----
    fmma24(sRbfA, sW, lane, arow0, col0, acc);
    {
        float2 bias[8];
#pragma unroll
        for (int nt = 0; nt < 8; nt++) bias[nt] = *(const float2*)&bemb[col0 + nt * 8 + cc * 2];
#pragma unroll
        for (int mt = 0; mt < 2; mt++)
#pragma unroll
            for (int h = 0; h < 2; h++) {
                int r = arow0 + mt * 16 + q + h * 8;
#pragma unroll
                for (int nt = 0; nt < 8; nt++) {
                    int c = col0 + nt * 8 + cc * 2;
                    sA[r * 260 + c]     = tf32r(fmaxf(acc[mt][nt][h * 2 + 0] + bias[nt].x, 0.f));
                    sA[r * 260 + c + 1] = tf32r(fmaxf(acc[mt][nt][h * 2 + 1] + bias[nt].y, 0.f));
                }
            }
    }
    __syncthreads();

    // ---- stage 2: sM = round(sA@Wpre2 + sM) ----
    mma_loop(sA, 260, sW, sWu, g_Wpre2, tid, lane, arow0, col0, acc);
#pragma unroll
    for (int mt = 0; mt < 2; mt++)
#pragma unroll
        for (int h = 0; h < 2; h++) {
            int r = arow0 + mt * 16 + q + h * 8;
#pragma unroll
            for (int nt = 0; nt < 8; nt++) {
                int c = col0 + nt * 8 + cc * 2;
                float* p = &sM[r * 260 + c];
                p[0] = tf32r(acc[mt][nt][h * 2 + 0] + p[0]);
                p[1] = tf32r(acc[mt][nt][h * 2 + 1] + p[1]);
            }
        }
    __syncthreads();

    // ---- stage 3: sA = round(silu(sM@Ws1 + bs1)) ----
    mma_loop(sM, 260, sW, sWu, g_Ws1, tid, lane, arow0, col0, acc);
    {
        float2 bias[8];
#pragma unroll
        for (int nt = 0; nt < 8; nt++) bias[nt] = *(const float2*)&bs1[col0 + nt * 8 + cc * 2];
#pragma unroll
        for (int mt = 0; mt < 2; mt++)
#pragma unroll
            for (int h = 0; h < 2; h++) {
                int r = arow0 + mt * 16 + q + h * 8;
#pragma unroll
                for (int nt = 0; nt < 8; nt++) {
                    int c = col0 + nt * 8 + cc * 2;
                    float m0 = acc[mt][nt][h * 2 + 0] + bias[nt].x;
                    float m1 = acc[mt][nt][h * 2 + 1] + bias[nt].y;
                    sA[r * 260 + c]     = tf32r(__fdividef(m0, 1.f + __expf(-m0)));
                    sA[r * 260 + c + 1] = tf32r(__fdividef(m1, 1.f + __expf(-m1)));
                }
            }
    }
    __syncthreads();

    // ---- stage 4: three 256-col chunks of Ws2, fused with f = rbf@Wlin ----
    for (int ch = 0; ch < 3; ch++) {
        mma_loop(sA, 260, sW, sWu, g_Ws2 + ch * 65536, tid, lane, arow0, col0, acc);
        // Wlin chunk into sW rows 0..19 (stride 264), zero rows 20..23
#pragma unroll
        for (int j = 0; j < 5; j++) {
            int v = tid + j * 256, row = v >> 6, c4 = (v & 63) * 4;
            *(float4*)&sW[row * 264 + c4] = *(const float4*)&g_Wlin[row * 768 + ch * 256 + c4];
        }
        { int row = 20 + (tid >> 6), c4 = (tid & 63) * 4;
          *(float4*)&sW[row * 264 + c4] = make_float4(0.f, 0.f, 0.f, 0.f); }
        __syncthreads();
        float facc[2][8][4];
        fmma24(sRbfA, sW, lane, arow0, col0, facc);
        float2 bias[8];
#pragma unroll
        for (int nt = 0; nt < 8; nt++)
            bias[nt] = *(const float2*)&bs2[ch * 256 + col0 + nt * 8 + cc * 2];

        if (ch == 0) {
            // g_state -> sM
#pragma unroll
            for (int mt = 0; mt < 2; mt++)
#pragma unroll
                for (int h = 0; h < 2; h++) {
                    int r = arow0 + mt * 16 + q + h * 8;
#pragma unroll
                    for (int nt = 0; nt < 8; nt++) {
                        int c = col0 + nt * 8 + cc * 2;
                        sM[r * 260 + c]     = (acc[mt][nt][h * 2 + 0] + bias[nt].x) * facc[mt][nt][h * 2 + 0];
                        sM[r * 260 + c + 1] = (acc[mt][nt][h * 2 + 1] + bias[nt].y) * facc[mt][nt][h * 2 + 1];
                    }
                }
            __syncthreads();
        } else if (ch == 1) {
            // g_edge: segmented mv scatter, two 128-col passes using sW as ge scratch
            __syncthreads();  // all warps done reading Wlin from sW
            for (int half = 0; half < 2; half++) {
                int colbase = half * 128;
                if (col0 >= colbase && col0 < colbase + 128) {
#pragma unroll
                    for (int mt = 0; mt < 2; mt++)
#pragma unroll
                        for (int h = 0; h < 2; h++) {
                            int r = arow0 + mt * 16 + q + h * 8;
#pragma unroll
                            for (int nt = 0; nt < 8; nt++) {
                                int c = col0 + nt * 8 + cc * 2;
                                float g0 = (acc[mt][nt][h * 2 + 0] + bias[nt].x) * facc[mt][nt][h * 2 + 0];
                                float g1 = (acc[mt][nt][h * 2 + 1] + bias[nt].y) * facc[mt][nt][h * 2 + 1];
                                int off = c - colbase;
                                sW[r * 132 + off]     = g0;
                                sW[r * 132 + off + 1] = g1;
                            }
                        }
                }
                __syncthreads();
                if (tid < 128) {
                    int c = colbase + tid;
                    int dprev = sDst[0];
                    float Sgs = 0.f, S0 = 0.f, S1 = 0.f, S2 = 0.f;
                    for (int r = 0; r < 64; r++) {
                        int d = sDst[r];
                        if (d != dprev) {
                            float xv = x[(size_t)dprev * 256 + c];
                            float* vb = out_v + (size_t)dprev * 768 + c;
                            atomicAdd(vb,       fmaf(xv, Sgs, S0));
                            atomicAdd(vb + 256, fmaf(xv, Sgs, S1));
                            atomicAdd(vb + 512, fmaf(xv, Sgs, S2));
                            Sgs = S0 = S1 = S2 = 0.f;
                            dprev = d;
                        }
                        float gs = sM[r * 260 + c];
                        float ge = sW[r * 132 + tid];
                        Sgs += gs;
                        S0 = fmaf(sEv[r * 3 + 0], ge, S0);
                        S1 = fmaf(sEv[r * 3 + 1], ge, S1);
                        S2 = fmaf(sEv[r * 3 + 2], ge, S2);
                    }
                    float xv = x[(size_t)dprev * 256 + c];
                    float* vb = out_v + (size_t)dprev * 768 + c;
                    atomicAdd(vb,       fmaf(xv, Sgs, S0));
                    atomicAdd(vb + 256, fmaf(xv, Sgs, S1));
                    atomicAdd(vb + 512, fmaf(xv, Sgs, S2));
                }
                __syncthreads();
            }
        } else {
            // ms stats: write to sA (free after final GEMM), segmented scan + coalesced flush
#pragma unroll
            for (int mt = 0; mt < 2; mt++)
#pragma unroll
                for (int h = 0; h < 2; h++) {
                    int r = arow0 + mt * 16 + q + h * 8;
#pragma unroll
                    for (int nt = 0; nt < 8; nt++) {
                        int c = col0 + nt * 8 + cc * 2;
                        sA[r * 260 + c]     = (acc[mt][nt][h * 2 + 0] + bias[nt].x) * facc[mt][nt][h * 2 + 0];
                        sA[r * 260 + c + 1] = (acc[mt][nt][h * 2 + 1] + bias[nt].y) * facc[mt][nt][h * 2 + 1];
                    }
                }
            __syncthreads();
            {
                int c = tid;
                int dprev = sDst[0];
                float S = 0.f, SS = 0.f;
                float mn = __int_as_float(0x7f800000), mx = __int_as_float(0xff800000);
                for (int r = 0; r < 64; r++) {
                    int d = sDst[r];
                    if (d != dprev) {
                        int a = dprev * 256 + c;
                        atomicAdd(&g_sum[a], S);
                        atomicAdd(&g_sumsq[a], SS);
                        atomicMaxF(&g_maxb[a], mx);
                        atomicMinF(&g_minb[a], mn);
                        S = SS = 0.f;
                        mn = __int_as_float(0x7f800000);
                        mx = __int_as_float(0xff800000);
                        dprev = d;
                    }
                    float v = sA[r * 260 + c];
                    S += v;
                    SS = fmaf(v, v, SS);
                    mn = fminf(mn, v);
                    mx = fmaxf(mx, v);
                }
                int a = dprev * 256 + c;
                atomicAdd(&g_sum[a], S);
                atomicAdd(&g_sumsq[a], SS);
                atomicMaxF(&g_maxb[a], mx);
                atomicMinF(&g_minb[a], mn);
            }
        }
    }
}

// ---------------- avg_log ----------------
__global__ void avglog_kernel() {
    __shared__ float red[256];
    float s = 0.f;
    for (int i = threadIdx.x; i < NN; i += 256) s += log1pf(g_deg[i]);
    red[threadIdx.x] = s;
    __syncthreads();
    for (int off = 128; off > 0; off >>= 1) {
        if (threadIdx.x < off) red[threadIdx.x] += red[threadIdx.x + off];
        __syncthreads();
    }
    if (threadIdx.x == 0) g_avglog = red[0] / (float)NN;
}

// ---------------- aggs -> g_cat (rounded) ----------------
__global__ void agg_kernel() {
    int idx = blockIdx.x * 256 + threadIdx.x;
    if (idx >= NN * FF) return;
    int n = idx >> 8;
    int c = idx & 255;
    float deg  = g_deg[n];
    float degc = fmaxf(deg, 1.f);
    float mean = g_sum[idx] / degc;
    float msq  = g_sumsq[idx] / degc;
    float stdv = sqrtf(fmaxf(msq - mean * mean, 0.f) + 1e-5f);
    float mn = (deg > 0.f) ? g_minb[idx] : 0.f;
    float mx = (deg > 0.f) ? g_maxb[idx] : 0.f;
    float avg  = g_avglog;
    float logd = log1pf(deg);
    float s1 = logd / avg;
    float s2 = avg / log1pf(degc);
    float* base = g_cat + (size_t)n * 3328 + 256 + c;
    base[0 * FF]  = tf32r(mean);      base[1 * FF]  = tf32r(mn);
    base[2 * FF]  = tf32r(mx);        base[3 * FF]  = tf32r(stdv);
    base[4 * FF]  = tf32r(mean * s1); base[5 * FF]  = tf32r(mn * s1);
    base[6 * FF]  = tf32r(mx * s1);   base[7 * FF]  = tf32r(stdv * s1);
    base[8 * FF]  = tf32r(mean * s2); base[9 * FF]  = tf32r(mn * s2);
    base[10 * FF] = tf32r(mx * s2);   base[11 * FF] = tf32r(stdv * s2);
}

// ---------------- post GEMM: out_x = x + g_cat @ Wpost + bpost (tf32 mma, packed W) ----------------
__global__ __launch_bounds__(256) void gemm_post_kernel(const float* __restrict__ x,
                                                        const float* __restrict__ bpost,
                                                        float* __restrict__ out_x) {
    __shared__ float sW[2 * 4224];
    __shared__ float sAt[2 * 64 * 20];
    uint32_t sWu = (uint32_t)__cvta_generic_to_shared(sW);
    uint32_t sAu = (uint32_t)__cvta_generic_to_shared(sAt);

    int tid = threadIdx.x, lane = tid & 31, w = tid >> 5;
    int arow0 = (w & 1) * 32, col0 = (w >> 1) * 64;
    int q = lane >> 2, cc = lane & 3;
    int n0 = blockIdx.x * 64;

    float acc[2][8][4];
#pragma unroll
    for (int mt = 0; mt < 2; mt++)
#pragma unroll
        for (int nt = 0; nt < 8; nt++)
#pragma unroll
            for (int z = 0; z < 4; z++) acc[mt][nt][z] = 0.f;

    int arow = tid >> 2, ac4 = (tid & 3) * 4;
    int asrc_n = min(n0 + arow, NN - 1);

    {
#pragma unroll
        for (int qq = 0; qq < 4; qq++) {
            int v = qq * 256 + tid, r8 = v >> 7, c4 = (v & 127) * 4;
            cp16(sWu + (uint32_t)((r8 * 528 + c4) * 4), g_Wpost + v * 4);
        }
        cp16(sAu + (uint32_t)((arow * 20 + ac4) * 4), g_cat + (size_t)asrc_n * 3328 + ac4);
        cp_commit();
    }
    const int KT = 3328 / 16;  // 208
    for (int t = 0; t < KT; t++) {
        if (t + 1 < KT) {
            const float* wsrc = g_Wpost + (size_t)(t + 1) * 4096;
            uint32_t wb = sWu + (uint32_t)((((t + 1) & 1) * 4224) * 4);
            uint32_t ab = sAu + (uint32_t)((((t + 1) & 1) * 64 * 20) * 4);
#pragma unroll
            for (int qq = 0; qq < 4; qq++) {
                int v = qq * 256 + tid, r8 = v >> 7, c4 = (v & 127) * 4;
                cp16(wb + (uint32_t)((r8 * 528 + c4) * 4), wsrc + v * 4);
            }
            cp16(ab + (uint32_t)((arow * 20 + ac4) * 4),
                 g_cat + (size_t)asrc_n * 3328 + (t + 1) * 16 + ac4);
            cp_commit();
            cp_wait1();
        } else {
            cp_wait0();
        }
        __syncthreads();
        compute_k16(sAt + (t & 1) * 64 * 20, 20, arow0, 0, sW + (t & 1) * 4224,
                    lane, col0, acc);
        __syncthreads();
    }

#pragma unroll
    for (int mt = 0; mt < 2; mt++)
#pragma unroll
        for (int h = 0; h < 2; h++) {
            int r = arow0 + mt * 16 + q + h * 8;
            int n = n0 + r;
            if (n < NN) {
#pragma unroll
                for (int nt = 0; nt < 8; nt++) {
                    int c = col0 + nt * 8 + cc * 2;
                    float2 xv = *(const float2*)&x[(size_t)n * 256 + c];
                    float2 bb = *(const float2*)&bpost[c];
                    float2 o;
                    o.x = xv.x + acc[mt][nt][h * 2 + 0] + bb.x;
                    o.y = xv.y + acc[mt][nt][h * 2 + 1] + bb.y;
                    *(float2*)&out_x[(size_t)n * 256 + c] = o;
                }
            }
        }
}

// ---------------- launch ----------------
extern "C" void kernel_launch(void* const* d_in, const int* in_sizes, int n_in,
                              void* d_out, int out_size) {
    const float* x        = (const float*)d_in[0];
    const float* v        = (const float*)d_in[1];
    const float* edge_rbf = (const float*)d_in[2];
    const float* edge_vec = (const float*)d_in[3];
    const float* Wemb     = (const float*)d_in[4];
    const float* bemb     = (const float*)d_in[5];
    const float* Wpre     = (const float*)d_in[6];
    const float* bpre     = (const float*)d_in[7];
    const float* Ws1      = (const float*)d_in[8];
    const float* bs1      = (const float*)d_in[9];
    const float* Ws2      = (const float*)d_in[10];
    const float* bs2      = (const float*)d_in[11];
    const float* Wlin     = (const float*)d_in[12];
    const float* Wpost    = (const float*)d_in[13];
    const float* bpost    = (const float*)d_in[14];
    const int*   eidx     = (const int*)d_in[15];

    float* out_x = (float*)d_out;
    float* out_v = out_x + (size_t)NN * FF;

    cudaFuncSetAttribute(edge_kernel, cudaFuncAttributeMaxDynamicSharedMemorySize,
                         EDGE_SMEM_BYTES);

    cudaMemcpyAsync(out_v, v, (size_t)NN * 3 * FF * sizeof(float), cudaMemcpyDeviceToDevice);

    cvt_kernel<<<(3328 * FF + 255) / 256, 256>>>(Wemb, Wpre, Ws1, Ws2, Wlin, Wpost);
    init_kernel<<<(NN * FF + 255) / 256, 256>>>(x);
    hist_kernel<<<NCHUNK, 256>>>(eidx);
    scanA_kernel<<<(NN + 255) / 256, 256>>>();
    scanB_kernel<<<1, 256>>>();
    scatter_kernel<<<NCHUNK, 256>>>(eidx);
    gemm_pre_kernel<<<dim3((NN + 63) / 64, 2), 256>>>(x, Wpre);
    edge_kernel<<<EE / TE, 256, EDGE_SMEM_BYTES>>>(x, edge_rbf, edge_vec,
                                                   bemb, bpre, bs1, bs2, out_v);
    avglog_kernel<<<1, 256>>>();
    agg_kernel<<<(NN * FF + 255) / 256, 256>>>();
    gemm_post_kernel<<<(NN + 63) / 64, 256>>>(x, bpost, out_x);
}

// round 14
// speedup vs baseline: 1.1835x; 1.1835x over previous
#include <cuda_runtime.h>
#include <math.h>
#include <stdint.h>

#define NN 10000
#define EE 160000
#define FF 256
#define RR 20
#define TE 64
#define CHUNK 2048
#define NCHUNK 79   // ceil(EE / CHUNK)

// ---------------- device scratch ----------------
__device__ float g_P0[NN * FF];
__device__ float g_P1[NN * FF];
__device__ float g_sum[NN * FF];
__device__ float g_sumsq[NN * FF];
__device__ float g_minb[NN * FF];
__device__ float g_maxb[NN * FF];
__device__ float g_deg[NN];
__device__ float g_avglog;
__device__ float g_cat[NN * 3328];
// sort scratch
__device__ int g_chunkCnt[NCHUNK * NN];
__device__ int g_binCnt[NN];
__device__ int g_binBase[NN];
__device__ int g_perm[EE];
__device__ int g_ssrc[EE];
__device__ int g_sdst[EE];
// tf32-rounded weight copies (row-major, unpacked)
__device__ float g_Wemb[RR * FF];
__device__ float g_Wpre0[FF * FF];
__device__ float g_Wpre1[FF * FF];
__device__ float g_Wpre2[FF * FF];
__device__ float g_Ws1[FF * FF];
__device__ float g_Ws2[FF * 3 * FF];
__device__ float g_Wlin[RR * 3 * FF];
__device__ float g_Wpost[3328 * FF];

// ---------------- helpers ----------------
__device__ __forceinline__ float tf32r(float x) {
    uint32_t u;
    asm("cvt.rna.tf32.f32 %0, %1;" : "=r"(u) : "f"(x));
    return __uint_as_float(u);
}
__device__ __forceinline__ uint32_t F2U(float f) { return __float_as_uint(f); }

__device__ __forceinline__ void mma8(float c[4], uint32_t a0, uint32_t a1, uint32_t a2,
                                     uint32_t a3, uint32_t b0, uint32_t b1) {
    asm volatile(
        "mma.sync.aligned.m16n8k8.row.col.f32.tf32.tf32.f32 "
        "{%0,%1,%2,%3},{%4,%5,%6,%7},{%8,%9},{%0,%1,%2,%3};"
        : "+f"(c[0]), "+f"(c[1]), "+f"(c[2]), "+f"(c[3])
        : "r"(a0), "r"(a1), "r"(a2), "r"(a3), "r"(b0), "r"(b1));
}

__device__ __forceinline__ void cp16(uint32_t saddr, const void* g) {
    asm volatile("cp.async.ca.shared.global [%0], [%1], 16;" :: "r"(saddr), "l"(g));
}
__device__ __forceinline__ void cp_commit() { asm volatile("cp.async.commit_group;"); }
__device__ __forceinline__ void cp_wait1()  { asm volatile("cp.async.wait_group 1;"); }
__device__ __forceinline__ void cp_wait0()  { asm volatile("cp.async.wait_group 0;"); }

__device__ __forceinline__ void atomicMaxF(float* p, float v) {
    if (v >= 0.f) atomicMax((int*)p, __float_as_int(v));
    else          atomicMin((unsigned int*)p, __float_as_uint(v));
}
__device__ __forceinline__ void atomicMinF(float* p, float v) {
    if (v >= 0.f) atomicMin((int*)p, __float_as_int(v));
    else          atomicMax((unsigned int*)p, __float_as_uint(v));
}

// ---------------- weight conversion ----------------
__global__ void cvt_kernel(const float* __restrict__ Wemb, const float* __restrict__ Wpre,
                           const float* __restrict__ Ws1, const float* __restrict__ Ws2,
                           const float* __restrict__ Wlin, const float* __restrict__ Wpost) {
    int i = blockIdx.x * 256 + threadIdx.x;
    if (i < RR * FF)     g_Wemb[i]  = tf32r(Wemb[i]);
    if (i < FF * FF) {
        g_Wpre0[i] = tf32r(Wpre[i]);
        g_Wpre1[i] = tf32r(Wpre[FF * FF + i]);
        g_Wpre2[i] = tf32r(Wpre[2 * FF * FF + i]);
        g_Ws1[i]   = tf32r(Ws1[i]);
    }
    if (i < FF * 3 * FF) g_Ws2[i]   = tf32r(Ws2[i]);
    if (i < RR * 3 * FF) g_Wlin[i]  = tf32r(Wlin[i]);
    if (i < 3328 * FF)   g_Wpost[i] = tf32r(Wpost[i]);
}

// ---------------- init ----------------
__global__ void init_kernel(const float* __restrict__ x) {
    int i = blockIdx.x * 256 + threadIdx.x;
    if (i < NN * FF) {
        g_sum[i]   = 0.f;
        g_sumsq[i] = 0.f;
        g_minb[i]  = __int_as_float(0x7f800000);
        g_maxb[i]  = __int_as_float(0xff800000);
        int n = i >> 8, c = i & 255;
        g_cat[n * 3328 + c] = tf32r(x[i]);
    }
}

// ---------------- sort: per-chunk histogram (2048-edge chunks) ----------------
__global__ __launch_bounds__(256) void hist_kernel(const int* __restrict__ eidx) {
    __shared__ int shist[NN];
    int b = blockIdx.x, t = threadIdx.x;
    for (int i = t; i < NN; i += 256) shist[i] = 0;
    __syncthreads();
    int ebase = b * CHUNK;
#pragma unroll
    for (int j = 0; j < CHUNK / 256; j++) {
        int e = ebase + j * 256 + t;
        if (e < EE) atomicAdd(&shist[eidx[EE + e]], 1);
    }
    __syncthreads();
    for (int i = t; i < NN; i += 256) g_chunkCnt[b * NN + i] = shist[i];
}

// ---------------- sort: per-bin scan over chunks ----------------
__global__ void scanA_kernel() {
    int d = blockIdx.x * 256 + threadIdx.x;
    if (d >= NN) return;
    int run = 0;
    for (int b = 0; b < NCHUNK; b++) {
        int idx = b * NN + d;
        int t = g_chunkCnt[idx];
        g_chunkCnt[idx] = run;
        run += t;
    }
    g_binCnt[d] = run;
    g_deg[d] = (float)run;
}

// ---------------- sort: exclusive scan over bins + avg_log (single block) ----------------
__global__ void scanB_kernel() {
    __shared__ int sp[256];
    __shared__ float sf[256];
    int t = threadIdx.x;
    int lo = t * 40, hi = min(lo + 40, NN);
    int s = 0;
    float ls = 0.f;
    for (int i = lo; i < hi; i++) {
        int c = g_binCnt[i];
        s += c;
        ls += log1pf((float)c);
    }
    sp[t] = s;
    sf[t] = ls;
    __syncthreads();
    for (int off = 1; off < 256; off <<= 1) {
        int v = (t >= off) ? sp[t - off] : 0;
        __syncthreads();
        sp[t] += v;
        __syncthreads();
    }
    int base = (t > 0) ? sp[t - 1] : 0;
    for (int i = lo; i < hi; i++) {
        int c = g_binCnt[i];
        g_binBase[i] = base;
        base += c;
    }
    // avg_log reduction
    for (int off = 128; off > 0; off >>= 1) {
        if (t < off) sf[t] += sf[t + off];
        __syncthreads();
    }
    if (t == 0) g_avglog = sf[0] / (float)NN;
}

// ---------------- sort: stable scatter (8 rounds of 256 per chunk) ----------------
__global__ __launch_bounds__(256) void scatter_kernel(const int* __restrict__ eidx) {
    __shared__ int rc[NN];
    __shared__ int sd[256];
    int b = blockIdx.x, t = threadIdx.x;
    for (int i = t; i < NN; i += 256) rc[i] = 0;
    __syncthreads();
    int ebase = b * CHUNK;
#pragma unroll
    for (int j = 0; j < CHUNK / 256; j++) {
        int e = ebase + j * 256 + t;
        int d = (e < EE) ? eidx[EE + e] : -1;
        sd[t] = d;
        __syncthreads();
        if (d >= 0) {
            int rank = 0;
            for (int k = 0; k < t; k++) rank += (sd[k] == d);
            int pos = g_binBase[d] + g_chunkCnt[b * NN + d] + rc[d] + rank;
            g_perm[pos] = e;
            g_ssrc[pos] = eidx[e];
            g_sdst[pos] = d;
        }
        __syncthreads();
        if (d >= 0) atomicAdd(&rc[d], 1);
        __syncthreads();
    }
}

// ---------------- tf32 mma building blocks (warp 32x64, 8 warps; UNPACKED stride-264 B) ----------------
__device__ __forceinline__ void compute_k16(const float* sA, int astr, int arow0, int k0,
                                            const float* sWb, int lane, int col0,
                                            float acc[2][8][4]) {
    int q = lane >> 2, c = lane & 3;
#pragma unroll
    for (int ks = 0; ks < 16; ks += 8) {
        uint32_t a[2][4];
#pragma unroll
        for (int mt = 0; mt < 2; mt++) {
            const float* ap = sA + (arow0 + mt * 16 + q) * astr + k0 + ks + c;
            a[mt][0] = F2U(ap[0]);
            a[mt][2] = F2U(ap[4]);
            a[mt][1] = F2U(ap[8 * astr]);
            a[mt][3] = F2U(ap[8 * astr + 4]);
        }
#pragma unroll
        for (int nt = 0; nt < 8; nt++) {
            const float* bp = sWb + (ks + c) * 264 + col0 + nt * 8 + q;
            uint32_t b0 = F2U(bp[0]);
            uint32_t b1 = F2U(bp[4 * 264]);
            mma8(acc[0][nt], a[0][0], a[0][1], a[0][2], a[0][3], b0, b1);
            mma8(acc[1][nt], a[1][0], a[1][1], a[1][2], a[1][3], b0, b1);
        }
    }
}

__device__ __forceinline__ void mma_loop(const float* sA, int astr, float* sW, uint32_t sWu,
                                         const float* __restrict__ Wg, int wst,
                                         int tid, int lane, int arow0, int col0,
                                         float acc[2][8][4]) {
#pragma unroll
    for (int mt = 0; mt < 2; mt++)
#pragma unroll
        for (int nt = 0; nt < 8; nt++)
#pragma unroll
            for (int z = 0; z < 4; z++) acc[mt][nt][z] = 0.f;
    {
#pragma unroll
        for (int qq = 0; qq < 4; qq++) {
            int v = qq * 256 + tid, row = v >> 6, c4 = (v & 63) * 4;
            cp16(sWu + (uint32_t)((row * 264 + c4) * 4), Wg + row * wst + c4);
        }
        cp_commit();
    }
    for (int t = 0; t < 16; t++) {
        if (t + 1 < 16) {
            const float* src = Wg + (t + 1) * 16 * wst;
            uint32_t dbase = sWu + (uint32_t)((((t + 1) & 1) * 16 * 264) * 4);
#pragma unroll
            for (int qq = 0; qq < 4; qq++) {
                int v = qq * 256 + tid, row = v >> 6, c4 = (v & 63) * 4;
                cp16(dbase + (uint32_t)((row * 264 + c4) * 4), src + row * wst + c4);
            }
            cp_commit();
            cp_wait1();
        } else {
            cp_wait0();
        }
        __syncthreads();
        compute_k16(sA, astr, arow0, t * 16, sW + (t & 1) * 16 * 264, lane, col0, acc);
        __syncthreads();
    }
}

__device__ __forceinline__ void fmma24(const float* sRbfA, const float* sW, int lane,
                                       int arow0, int col0, float facc[2][8][4]) {
#pragma unroll
    for (int mt = 0; mt < 2; mt++)
#pragma unroll
        for (int nt = 0; nt < 8; nt++)
#pragma unroll
            for (int z = 0; z < 4; z++) facc[mt][nt][z] = 0.f;
    int q = lane >> 2, c = lane & 3;
#pragma unroll
    for (int ks = 0; ks < 24; ks += 8) {
        uint32_t a[2][4];
#pragma unroll
        for (int mt = 0; mt < 2; mt++) {
            const float* ap = sRbfA + (arow0 + mt * 16 + q) * 28 + ks + c;
            a[mt][0] = F2U(ap[0]);
            a[mt][2] = F2U(ap[4]);
            a[mt][1] = F2U(ap[8 * 28]);
            a[mt][3] = F2U(ap[8 * 28 + 4]);
        }
#pragma unroll
        for (int nt = 0; nt < 8; nt++) {
            const float* bp = sW + (ks + c) * 264 + col0 + nt * 8 + q;
            uint32_t b0 = F2U(bp[0]);
            uint32_t b1 = F2U(bp[4 * 264]);
            mma8(facc[0][nt], a[0][0], a[0][1], a[0][2], a[0][3], b0, b1);
            mma8(facc[1][nt], a[1][0], a[1][1], a[1][2], a[1][3], b0, b1);
        }
    }
}

// ---------------- node precompute P0/P1 (tf32 mma; A streamed from g_cat cols 0..255) ----------------
__global__ __launch_bounds__(256) void gemm_pre_kernel() {
    __shared__ float sW[2 * 16 * 264];
    __shared__ float sAt[2 * 64 * 20];
    uint32_t sWu = (uint32_t)__cvta_generic_to_shared(sW);
    uint32_t sAu = (uint32_t)__cvta_generic_to_shared(sAt);

    const float* Wg = blockIdx.y ? g_Wpre1 : g_Wpre0;
    float* P = blockIdx.y ? g_P1 : g_P0;

    int tid = threadIdx.x, lane = tid & 31, w = tid >> 5;
    int arow0 = (w & 1) * 32, col0 = (w >> 1) * 64;
    int q = lane >> 2, cc = lane & 3;
    int n0 = blockIdx.x * 64;

    float acc[2][8][4];
#pragma unroll
    for (int mt = 0; mt < 2; mt++)
#pragma unroll
        for (int nt = 0; nt < 8; nt++)
#pragma unroll
            for (int z = 0; z < 4; z++) acc[mt][nt][z] = 0.f;

    int arow = tid >> 2, ac4 = (tid & 3) * 4;
    int asrc_n = min(n0 + arow, NN - 1);

    {
#pragma unroll
        for (int qq = 0; qq < 4; qq++) {
            int v = qq * 256 + tid, row = v >> 6, c4 = (v & 63) * 4;
            cp16(sWu + (uint32_t)((row * 264 + c4) * 4), Wg + row * 256 + c4);
        }
        cp16(sAu + (uint32_t)((arow * 20 + ac4) * 4), g_cat + (size_t)asrc_n * 3328 + ac4);
        cp_commit();
    }
    const int KT = 16;
    for (int t = 0; t < KT; t++) {
        if (t + 1 < KT) {
            int k0 = (t + 1) * 16;
            const float* wsrc = Wg + (size_t)k0 * 256;
            uint32_t wb = sWu + (uint32_t)((((t + 1) & 1) * 16 * 264) * 4);
            uint32_t ab = sAu + (uint32_t)((((t + 1) & 1) * 64 * 20) * 4);
#pragma unroll
            for (int qq = 0; qq < 4; qq++) {
                int v = qq * 256 + tid, row = v >> 6, c4 = (v & 63) * 4;
                cp16(wb + (uint32_t)((row * 264 + c4) * 4), wsrc + row * 256 + c4);
            }
            cp16(ab + (uint32_t)((arow * 20 + ac4) * 4),
                 g_cat + (size_t)asrc_n * 3328 + k0 + ac4);
            cp_commit();
            cp_wait1();
        } else {
            cp_wait0();
        }
        __syncthreads();
        compute_k16(sAt + (t & 1) * 64 * 20, 20, arow0, 0, sW + (t & 1) * 16 * 264,
                    lane, col0, acc);
        __syncthreads();
    }

#pragma unroll
    for (int mt = 0; mt < 2; mt++)
#pragma unroll
        for (int h = 0; h < 2; h++) {
            int r = arow0 + mt * 16 + q + h * 8;
            int n = n0 + r;
            if (n < NN) {
#pragma unroll
                for (int nt = 0; nt < 8; nt++) {
                    int c = col0 + nt * 8 + cc * 2;
                    float2 o;
                    o.x = acc[mt][nt][h * 2 + 0];
                    o.y = acc[mt][nt][h * 2 + 1];
                    *(float2*)&P[(size_t)n * 256 + c] = o;
                }
            }
        }
}

// ---------------- fused edge kernel (256 threads; sorted edges; segmented epilogues) ----------------
// smem floats: sA 64x260 | sM 64x260 | sW 2x16x264 | sRbfA 64x28 | sEv 192 | src/dst/perm 192 ints
#define EDGE_SMEM_FLOATS (16640 + 16640 + 8448 + 1792 + 192 + 192)
#define EDGE_SMEM_BYTES (EDGE_SMEM_FLOATS * 4)

__global__ __launch_bounds__(256, 1) void edge_kernel(
    const float* __restrict__ x, const float* __restrict__ edge_rbf,
    const float* __restrict__ edge_vec,
    const float* __restrict__ bemb, const float* __restrict__ bpre,
    const float* __restrict__ bs1, const float* __restrict__ bs2,
    float* __restrict__ out_v) {
    extern __shared__ float sm[];
    float* sA    = sm;
    float* sM    = sm + 16640;
    float* sW    = sm + 33280;
    float* sRbfA = sm + 41728;
    float* sEv   = sm + 43520;
    int* sSrc  = (int*)(sm + 43712);
    int* sDst  = sSrc + 64;
    int* sPerm = sDst + 64;
    uint32_t sWu = (uint32_t)__cvta_generic_to_shared(sW);

    int tid = threadIdx.x, lane = tid & 31, w = tid >> 5;
    int arow0 = (w & 1) * 32, col0 = (w >> 1) * 64;
    int q = lane >> 2, cc = lane & 3;
    int e0 = blockIdx.x * TE;

    if (tid < TE) {
        sSrc[tid]  = g_ssrc[e0 + tid];
        sDst[tid]  = g_sdst[e0 + tid];
        sPerm[tid] = g_perm[e0 + tid];
    }
    __syncthreads();

    // rbf gather (via perm), tf32-rounded, padded to 24 cols (stride 28)
#pragma unroll
    for (int j = 0; j < 5; j++) {
        int i = tid + j * 256;
        int e = i / 20, k = i - e * 20;
        sRbfA[e * 28 + k] = tf32r(edge_rbf[(size_t)sPerm[e] * RR + k]);
    }
    { int e = tid >> 2, k = 20 + (tid & 3); sRbfA[e * 28 + k] = 0.f; }
    if (tid < 192) {
        int e = tid / 3, comp = tid - e * 3;
        sEv[tid] = edge_vec[(size_t)sPerm[e] * 3 + comp];
    }
    // Wemb -> sW rows 0..19, zero rows 20..23
#pragma unroll
    for (int j = 0; j < 5; j++) {
        int v = tid + j * 256, row = v >> 6, c4 = (v & 63) * 4;
        *(float4*)&sW[row * 264 + c4] = *(const float4*)&g_Wemb[row * 256 + c4];
    }
    { int row = 20 + (tid >> 6), c4 = (tid & 63) * 4;
      *(float4*)&sW[row * 264 + c4] = make_float4(0.f, 0.f, 0.f, 0.f); }
    __syncthreads();

    // prefill sM = P0[src] + P1[dst] + bpre (4096 float4s)
#pragma unroll
    for (int j = 0; j < 16; j++) {
        int f = (tid + j * 256) * 4;
        int r = f >> 8, c = f & 255;
        int s = sSrc[r], d = sDst[r];
        float4 p0 = *(const float4*)&g_P0[s * 256 + c];
        float4 p1 = *(const float4*)&g_P1[d * 256 + c];
        float4 bb = *(const float4*)&bpre[c];
        *(float4*)&sM[r * 260 + c] =
            make_float4(p0.x + p1.x + bb.x, p0.y + p1.y + bb.y,
                        p0.z + p1.z + bb.z, p0.w + p1.w + bb.w);
    }

    float acc[2][8][4];

    // ---- stage 1: sA = round(relu(rbf@Wemb + bemb)) ----
    fmma24(sRbfA, sW, lane, arow0, col0, acc);
    {
        float2 bias[8];
#pragma unroll
        for (int nt = 0; nt < 8; nt++) bias[nt] = *(const float2*)&bemb[col0 + nt * 8 + cc * 2];
#pragma unroll
        for (int mt = 0; mt < 2; mt++)
#pragma unroll
            for (int h = 0; h < 2; h++) {
                int r = arow0 + mt * 16 + q + h * 8;
#pragma unroll
                for (int nt = 0; nt < 8; nt++) {
                    int c = col0 + nt * 8 + cc * 2;
                    sA[r * 260 + c]     = tf32r(fmaxf(acc[mt][nt][h * 2 + 0] + bias[nt].x, 0.f));
                    sA[r * 260 + c + 1] = tf32r(fmaxf(acc[mt][nt][h * 2 + 1] + bias[nt].y, 0.f));
                }
            }
    }
    __syncthreads();

    // ---- stage 2: sM = round(sA@Wpre2 + sM) ----
    mma_loop(sA, 260, sW, sWu, g_Wpre2, 256, tid, lane, arow0, col0, acc);
#pragma unroll
    for (int mt = 0; mt < 2; mt++)
#pragma unroll
        for (int h = 0; h < 2; h++) {
            int r = arow0 + mt * 16 + q + h * 8;
#pragma unroll
            for (int nt = 0; nt < 8; nt++) {
                int c = col0 + nt * 8 + cc * 2;
                float* p = &sM[r * 260 + c];
                p[0] = tf32r(acc[mt][nt][h * 2 + 0] + p[0]);
                p[1] = tf32r(acc[mt][nt][h * 2 + 1] + p[1]);
            }
        }
    __syncthreads();

    // ---- stage 3: sA = round(silu(sM@Ws1 + bs1)) ----
    mma_loop(sM, 260, sW, sWu, g_Ws1, 256, tid, lane, arow0, col0, acc);
    {
        float2 bias[8];
#pragma unroll
        for (int nt = 0; nt < 8; nt++) bias[nt] = *(const float2*)&bs1[col0 + nt * 8 + cc * 2];
#pragma unroll
        for (int mt = 0; mt < 2; mt++)
#pragma unroll
            for (int h = 0; h < 2; h++) {
                int r = arow0 + mt * 16 + q + h * 8;
#pragma unroll
                for (int nt = 0; nt < 8; nt++) {
                    int c = col0 + nt * 8 + cc * 2;
                    float m0 = acc[mt][nt][h * 2 + 0] + bias[nt].x;
                    float m1 = acc[mt][nt][h * 2 + 1] + bias[nt].y;
                    sA[r * 260 + c]     = tf32r(__fdividef(m0, 1.f + __expf(-m0)));
                    sA[r * 260 + c + 1] = tf32r(__fdividef(m1, 1.f + __expf(-m1)));
                }
            }
    }
    __syncthreads();

    // ---- stage 4: three 256-col chunks of Ws2, fused with f = rbf@Wlin ----
    for (int ch = 0; ch < 3; ch++) {
        mma_loop(sA, 260, sW, sWu, g_Ws2 + ch * 256, 768, tid, lane, arow0, col0, acc);
        // Wlin chunk into sW rows 0..19, zero rows 20..23
#pragma unroll
        for (int j = 0; j < 5; j++) {
            int v = tid + j * 256, row = v >> 6, c4 = (v & 63) * 4;
            *(float4*)&sW[row * 264 + c4] = *(const float4*)&g_Wlin[row * 768 + ch * 256 + c4];
        }
        { int row = 20 + (tid >> 6), c4 = (tid & 63) * 4;
          *(float4*)&sW[row * 264 + c4] = make_float4(0.f, 0.f, 0.f, 0.f); }
        __syncthreads();
        float facc[2][8][4];
        fmma24(sRbfA, sW, lane, arow0, col0, facc);
        float2 bias[8];
#pragma unroll
        for (int nt = 0; nt < 8; nt++)
            bias[nt] = *(const float2*)&bs2[ch * 256 + col0 + nt * 8 + cc * 2];

        if (ch == 0) {
            // g_state -> sM
#pragma unroll
            for (int mt = 0; mt < 2; mt++)
#pragma unroll
                for (int h = 0; h < 2; h++) {
                    int r = arow0 + mt * 16 + q + h * 8;
#pragma unroll
                    for (int nt = 0; nt < 8; nt++) {
                        int c = col0 + nt * 8 + cc * 2;
                        sM[r * 260 + c]     = (acc[mt][nt][h * 2 + 0] + bias[nt].x) * facc[mt][nt][h * 2 + 0];
                        sM[r * 260 + c + 1] = (acc[mt][nt][h * 2 + 1] + bias[nt].y) * facc[mt][nt][h * 2 + 1];
                    }
                }
            __syncthreads();
        } else if (ch == 1) {
            // g_edge: segmented mv scatter, two 128-col passes using sW as ge scratch
            __syncthreads();  // all warps done reading Wlin from sW
            for (int half = 0; half < 2; half++) {
                int colbase = half * 128;
                if (col0 >= colbase && col0 < colbase + 128) {
#pragma unroll
                    for (int mt = 0; mt < 2; mt++)
#pragma unroll
                        for (int h = 0; h < 2; h++) {
                            int r = arow0 + mt * 16 + q + h * 8;
#pragma unroll
                            for (int nt = 0; nt < 8; nt++) {
                                int c = col0 + nt * 8 + cc * 2;
                                float g0 = (acc[mt][nt][h * 2 + 0] + bias[nt].x) * facc[mt][nt][h * 2 + 0];
                                float g1 = (acc[mt][nt][h * 2 + 1] + bias[nt].y) * facc[mt][nt][h * 2 + 1];
                                int off = c - colbase;
                                sW[r * 132 + off]     = g0;
                                sW[r * 132 + off + 1] = g1;
                            }
                        }
                }
                __syncthreads();
                if (tid < 128) {
                    int c = colbase + tid;
                    int dprev = sDst[0];
                    float Sgs = 0.f, S0 = 0.f, S1 = 0.f, S2 = 0.f;
                    for (int r = 0; r < 64; r++) {
                        int d = sDst[r];
                        if (d != dprev) {
                            float xv = x[(size_t)dprev * 256 + c];
                            float* vb = out_v + (size_t)dprev * 768 + c;
                            atomicAdd(vb,       fmaf(xv, Sgs, S0));
                            atomicAdd(vb + 256, fmaf(xv, Sgs, S1));
                            atomicAdd(vb + 512, fmaf(xv, Sgs, S2));
                            Sgs = S0 = S1 = S2 = 0.f;
                            dprev = d;
                        }
                        float gs = sM[r * 260 + c];
                        float ge = sW[r * 132 + tid];
                        Sgs += gs;
                        S0 = fmaf(sEv[r * 3 + 0], ge, S0);
                        S1 = fmaf(sEv[r * 3 + 1], ge, S1);
                        S2 = fmaf(sEv[r * 3 + 2], ge, S2);
                    }
                    float xv = x[(size_t)dprev * 256 + c];
                    float* vb = out_v + (size_t)dprev * 768 + c;
                    atomicAdd(vb,       fmaf(xv, Sgs, S0));
                    atomicAdd(vb + 256, fmaf(xv, Sgs, S1));
                    atomicAdd(vb + 512, fmaf(xv, Sgs, S2));
                }
                __syncthreads();
            }
        } else {
            // ms stats: write to sA (free after final GEMM), segmented scan + coalesced flush
#pragma unroll
            for (int mt = 0; mt < 2; mt++)
#pragma unroll
                for (int h = 0; h < 2; h++) {
                    int r = arow0 + mt * 16 + q + h * 8;
#pragma unroll
                    for (int nt = 0; nt < 8; nt++) {
                        int c = col0 + nt * 8 + cc * 2;
                        sA[r * 260 + c]     = (acc[mt][nt][h * 2 + 0] + bias[nt].x) * facc[mt][nt][h * 2 + 0];
                        sA[r * 260 + c + 1] = (acc[mt][nt][h * 2 + 1] + bias[nt].y) * facc[mt][nt][h * 2 + 1];
                    }
                }
            __syncthreads();
            {
                int c = tid;
                int dprev = sDst[0];
                float S = 0.f, SS = 0.f;
                float mn = __int_as_float(0x7f800000), mx = __int_as_float(0xff800000);
                for (int r = 0; r < 64; r++) {
                    int d = sDst[r];
                    if (d != dprev) {
                        int a = dprev * 256 + c;
                        atomicAdd(&g_sum[a], S);
                        atomicAdd(&g_sumsq[a], SS);
                        atomicMaxF(&g_maxb[a], mx);
                        atomicMinF(&g_minb[a], mn);
                        S = SS = 0.f;
                        mn = __int_as_float(0x7f800000);
                        mx = __int_as_float(0xff800000);
                        dprev = d;
                    }
                    float v = sA[r * 260 + c];
                    S += v;
                    SS = fmaf(v, v, SS);
                    mn = fminf(mn, v);
                    mx = fmaxf(mx, v);
                }
                int a = dprev * 256 + c;
                atomicAdd(&g_sum[a], S);
                atomicAdd(&g_sumsq[a], SS);
                atomicMaxF(&g_maxb[a], mx);
                atomicMinF(&g_minb[a], mn);
            }
        }
    }
}

// ---------------- aggs -> g_cat (rounded) ----------------
__global__ void agg_kernel() {
    int idx = blockIdx.x * 256 + threadIdx.x;
    if (idx >= NN * FF) return;
    int n = idx >> 8;
    int c = idx & 255;
    float deg  = g_deg[n];
    float degc = fmaxf(deg, 1.f);
    float mean = g_sum[idx] / degc;
    float msq  = g_sumsq[idx] / degc;
    float stdv = sqrtf(fmaxf(msq - mean * mean, 0.f) + 1e-5f);
    float mn = (deg > 0.f) ? g_minb[idx] : 0.f;
    float mx = (deg > 0.f) ? g_maxb[idx] : 0.f;
    float avg  = g_avglog;
    float logd = log1pf(deg);
    float s1 = logd / avg;
    float s2 = avg / log1pf(degc);
    float* base = g_cat + (size_t)n * 3328 + 256 + c;
    base[0 * FF]  = tf32r(mean);      base[1 * FF]  = tf32r(mn);
    base[2 * FF]  = tf32r(mx);        base[3 * FF]  = tf32r(stdv);
    base[4 * FF]  = tf32r(mean * s1); base[5 * FF]  = tf32r(mn * s1);
    base[6 * FF]  = tf32r(mx * s1);   base[7 * FF]  = tf32r(stdv * s1);
    base[8 * FF]  = tf32r(mean * s2); base[9 * FF]  = tf32r(mn * s2);
    base[10 * FF] = tf32r(mx * s2);   base[11 * FF] = tf32r(stdv * s2);
}

// ---------------- post GEMM: out_x = x + g_cat @ Wpost + bpost (tf32 mma) ----------------
__global__ __launch_bounds__(256) void gemm_post_kernel(const float* __restrict__ x,
                                                        const float* __restrict__ bpost,
                                                        float* __restrict__ out_x) {
    __shared__ float sW[2 * 16 * 264];
    __shared__ float sAt[2 * 64 * 20];
    uint32_t sWu = (uint32_t)__cvta_generic_to_shared(sW);
    uint32_t sAu = (uint32_t)__cvta_generic_to_shared(sAt);

    int tid = threadIdx.x, lane = tid & 31, w = tid >> 5;
    int arow0 = (w & 1) * 32, col0 = (w >> 1) * 64;
    int q = lane >> 2, cc = lane & 3;
    int n0 = blockIdx.x * 64;

    float acc[2][8][4];
#pragma unroll
    for (int mt = 0; mt < 2; mt++)
#pragma unroll
        for (int nt = 0; nt < 8; nt++)
#pragma unroll
            for (int z = 0; z < 4; z++) acc[mt][nt][z] = 0.f;

    int arow = tid >> 2, ac4 = (tid & 3) * 4;
    int asrc_n = min(n0 + arow, NN - 1);

    {
#pragma unroll
        for (int qq = 0; qq < 4; qq++) {
            int v = qq * 256 + tid, row = v >> 6, c4 = (v & 63) * 4;
            cp16(sWu + (uint32_t)((row * 264 + c4) * 4), g_Wpost + row * 256 + c4);
        }
        cp16(sAu + (uint32_t)((arow * 20 + ac4) * 4), g_cat + (size_t)asrc_n * 3328 + ac4);
        cp_commit();
    }
    const int KT = 3328 / 16;
    for (int t = 0; t < KT; t++) {
        if (t + 1 < KT) {
            int k0 = (t + 1) * 16;
            const float* wsrc = g_Wpost + (size_t)k0 * 256;
            uint32_t wb = sWu + (uint32_t)((((t + 1) & 1) * 16 * 264) * 4);
            uint32_t ab = sAu + (uint32_t)((((t + 1) & 1) * 64 * 20) * 4);
#pragma unroll
            for (int qq = 0; qq < 4; qq++) {
                int v = qq * 256 + tid, row = v >> 6, c4 = (v & 63) * 4;
                cp16(wb + (uint32_t)((row * 264 + c4) * 4), wsrc + row * 256 + c4);
            }
            cp16(ab + (uint32_t)((arow * 20 + ac4) * 4),
                 g_cat + (size_t)asrc_n * 3328 + k0 + ac4);
            cp_commit();
            cp_wait1();
        } else {
            cp_wait0();
        }
        __syncthreads();
        compute_k16(sAt + (t & 1) * 64 * 20, 20, arow0, 0, sW + (t & 1) * 16 * 264,
                    lane, col0, acc);
        __syncthreads();
    }

#pragma unroll
    for (int mt = 0; mt < 2; mt++)
#pragma unroll
        for (int h = 0; h < 2; h++) {
            int r = arow0 + mt * 16 + q + h * 8;
            int n = n0 + r;
            if (n < NN) {
#pragma unroll
                for (int nt = 0; nt < 8; nt++) {
                    int c = col0 + nt * 8 + cc * 2;
                    float2 xv = *(const float2*)&x[(size_t)n * 256 + c];
                    float2 bb = *(const float2*)&bpost[c];
                    float2 o;
                    o.x = xv.x + acc[mt][nt][h * 2 + 0] + bb.x;
                    o.y = xv.y + acc[mt][nt][h * 2 + 1] + bb.y;
                    *(float2*)&out_x[(size_t)n * 256 + c] = o;
                }
            }
        }
}

// ---------------- launch ----------------
extern "C" void kernel_launch(void* const* d_in, const int* in_sizes, int n_in,
                              void* d_out, int out_size) {
    const float* x        = (const float*)d_in[0];
    const float* v        = (const float*)d_in[1];
    const float* edge_rbf = (const float*)d_in[2];
    const float* edge_vec = (const float*)d_in[3];
    const float* Wemb     = (const float*)d_in[4];
    const float* bemb     = (const float*)d_in[5];
    const float* Wpre     = (const float*)d_in[6];
    const float* bpre     = (const float*)d_in[7];
    const float* Ws1      = (const float*)d_in[8];
    const float* bs1      = (const float*)d_in[9];
    const float* Ws2      = (const float*)d_in[10];
    const float* bs2      = (const float*)d_in[11];
    const float* Wlin     = (const float*)d_in[12];
    const float* Wpost    = (const float*)d_in[13];
    const float* bpost    = (const float*)d_in[14];
    const int*   eidx     = (const int*)d_in[15];

    float* out_x = (float*)d_out;
    float* out_v = out_x + (size_t)NN * FF;

    cudaFuncSetAttribute(edge_kernel, cudaFuncAttributeMaxDynamicSharedMemorySize,
                         EDGE_SMEM_BYTES);

    cudaMemcpyAsync(out_v, v, (size_t)NN * 3 * FF * sizeof(float), cudaMemcpyDeviceToDevice);

    cvt_kernel<<<(3328 * FF + 255) / 256, 256>>>(Wemb, Wpre, Ws1, Ws2, Wlin, Wpost);
    init_kernel<<<(NN * FF + 255) / 256, 256>>>(x);
    hist_kernel<<<NCHUNK, 256>>>(eidx);
    scanA_kernel<<<(NN + 255) / 256, 256>>>();
    scanB_kernel<<<1, 256>>>();
    scatter_kernel<<<NCHUNK, 256>>>(eidx);
    gemm_pre_kernel<<<dim3((NN + 63) / 64, 2), 256>>>();
    edge_kernel<<<EE / TE, 256, EDGE_SMEM_BYTES>>>(x, edge_rbf, edge_vec,
                                                   bemb, bpre, bs1, bs2, out_v);
    agg_kernel<<<(NN * FF + 255) / 256, 256>>>();
    gemm_post_kernel<<<(NN + 63) / 64, 256>>>(x, bpost, out_x);
}

// round 15
// speedup vs baseline: 1.1953x; 1.0100x over previous
#include <cuda_runtime.h>
#include <math.h>
#include <stdint.h>

#define NN 10000
#define EE 160000
#define FF 256
#define RR 20
#define TE 32
#define CHUNK 2048
#define NCHUNK 79   // ceil(EE / CHUNK)

// ---------------- device scratch ----------------
__device__ float g_P0[NN * FF];
__device__ float g_P1[NN * FF];
__device__ float g_sum[NN * FF];
__device__ float g_sumsq[NN * FF];
__device__ float g_minb[NN * FF];
__device__ float g_maxb[NN * FF];
__device__ float g_deg[NN];
__device__ float g_avglog;
__device__ float g_cat[NN * 3328];
// sort scratch
__device__ int g_chunkCnt[NCHUNK * NN];
__device__ int g_binCnt[NN];
__device__ int g_binBase[NN];
__device__ int g_perm[EE];
__device__ int g_ssrc[EE];
__device__ int g_sdst[EE];
// tf32-rounded weight copies (row-major, unpacked)
__device__ float g_Wemb[RR * FF];
__device__ float g_Wpre0[FF * FF];
__device__ float g_Wpre1[FF * FF];
__device__ float g_Wpre2[FF * FF];
__device__ float g_Ws1[FF * FF];
__device__ float g_Ws2[FF * 3 * FF];
__device__ float g_Wlin[RR * 3 * FF];
__device__ float g_Wpost[3328 * FF];

// ---------------- helpers ----------------
__device__ __forceinline__ float tf32r(float x) {
    uint32_t u;
    asm("cvt.rna.tf32.f32 %0, %1;" : "=r"(u) : "f"(x));
    return __uint_as_float(u);
}
__device__ __forceinline__ uint32_t F2U(float f) { return __float_as_uint(f); }

__device__ __forceinline__ void mma8(float c[4], uint32_t a0, uint32_t a1, uint32_t a2,
                                     uint32_t a3, uint32_t b0, uint32_t b1) {
    asm volatile(
        "mma.sync.aligned.m16n8k8.row.col.f32.tf32.tf32.f32 "
        "{%0,%1,%2,%3},{%4,%5,%6,%7},{%8,%9},{%0,%1,%2,%3};"
        : "+f"(c[0]), "+f"(c[1]), "+f"(c[2]), "+f"(c[3])
        : "r"(a0), "r"(a1), "r"(a2), "r"(a3), "r"(b0), "r"(b1));
}

__device__ __forceinline__ void cp16(uint32_t saddr, const void* g) {
    asm volatile("cp.async.ca.shared.global [%0], [%1], 16;" :: "r"(saddr), "l"(g));
}
__device__ __forceinline__ void cp_commit() { asm volatile("cp.async.commit_group;"); }
__device__ __forceinline__ void cp_wait1()  { asm volatile("cp.async.wait_group 1;"); }
__device__ __forceinline__ void cp_wait0()  { asm volatile("cp.async.wait_group 0;"); }

__device__ __forceinline__ void atomicMaxF(float* p, float v) {
    if (v >= 0.f) atomicMax((int*)p, __float_as_int(v));
    else          atomicMin((unsigned int*)p, __float_as_uint(v));
}
__device__ __forceinline__ void atomicMinF(float* p, float v) {
    if (v >= 0.f) atomicMin((int*)p, __float_as_int(v));
    else          atomicMax((unsigned int*)p, __float_as_uint(v));
}

// ---------------- weight conversion ----------------
__global__ void cvt_kernel(const float* __restrict__ Wemb, const float* __restrict__ Wpre,
                           const float* __restrict__ Ws1, const float* __restrict__ Ws2,
                           const float* __restrict__ Wlin, const float* __restrict__ Wpost) {
    int i = blockIdx.x * 256 + threadIdx.x;
    if (i < RR * FF)     g_Wemb[i]  = tf32r(Wemb[i]);
    if (i < FF * FF) {
        g_Wpre0[i] = tf32r(Wpre[i]);
        g_Wpre1[i] = tf32r(Wpre[FF * FF + i]);
        g_Wpre2[i] = tf32r(Wpre[2 * FF * FF + i]);
        g_Ws1[i]   = tf32r(Ws1[i]);
    }
    if (i < FF * 3 * FF) g_Ws2[i]   = tf32r(Ws2[i]);
    if (i < RR * 3 * FF) g_Wlin[i]  = tf32r(Wlin[i]);
    if (i < 3328 * FF)   g_Wpost[i] = tf32r(Wpost[i]);
}

// ---------------- init ----------------
__global__ void init_kernel(const float* __restrict__ x) {
    int i = blockIdx.x * 256 + threadIdx.x;
    if (i < NN * FF) {
        g_sum[i]   = 0.f;
        g_sumsq[i] = 0.f;
        g_minb[i]  = __int_as_float(0x7f800000);
        g_maxb[i]  = __int_as_float(0xff800000);
        int n = i >> 8, c = i & 255;
        g_cat[n * 3328 + c] = tf32r(x[i]);
    }
}

// ---------------- sort: per-chunk histogram (2048-edge chunks) ----------------
__global__ __launch_bounds__(256) void hist_kernel(const int* __restrict__ eidx) {
    __shared__ int shist[NN];
    int b = blockIdx.x, t = threadIdx.x;
    for (int i = t; i < NN; i += 256) shist[i] = 0;
    __syncthreads();
    int ebase = b * CHUNK;
#pragma unroll
    for (int j = 0; j < CHUNK / 256; j++) {
        int e = ebase + j * 256 + t;
        if (e < EE) atomicAdd(&shist[eidx[EE + e]], 1);
    }
    __syncthreads();
    for (int i = t; i < NN; i += 256) g_chunkCnt[b * NN + i] = shist[i];
}

// ---------------- sort: per-bin scan over chunks ----------------
__global__ void scanA_kernel() {
    int d = blockIdx.x * 256 + threadIdx.x;
    if (d >= NN) return;
    int run = 0;
    for (int b = 0; b < NCHUNK; b++) {
        int idx = b * NN + d;
        int t = g_chunkCnt[idx];
        g_chunkCnt[idx] = run;
        run += t;
    }
    g_binCnt[d] = run;
    g_deg[d] = (float)run;
}

// ---------------- sort: exclusive scan over bins + avg_log (single block) ----------------
__global__ void scanB_kernel() {
    __shared__ int sp[256];
    __shared__ float sf[256];
    int t = threadIdx.x;
    int lo = t * 40, hi = min(lo + 40, NN);
    int s = 0;
    float ls = 0.f;
    for (int i = lo; i < hi; i++) {
        int c = g_binCnt[i];
        s += c;
        ls += log1pf((float)c);
    }
    sp[t] = s;
    sf[t] = ls;
    __syncthreads();
    for (int off = 1; off < 256; off <<= 1) {
        int v = (t >= off) ? sp[t - off] : 0;
        __syncthreads();
        sp[t] += v;
        __syncthreads();
    }
    int base = (t > 0) ? sp[t - 1] : 0;
    for (int i = lo; i < hi; i++) {
        int c = g_binCnt[i];
        g_binBase[i] = base;
        base += c;
    }
    for (int off = 128; off > 0; off >>= 1) {
        if (t < off) sf[t] += sf[t + off];
        __syncthreads();
    }
    if (t == 0) g_avglog = sf[0] / (float)NN;
}

// ---------------- sort: stable scatter (8 rounds of 256 per chunk) ----------------
__global__ __launch_bounds__(256) void scatter_kernel(const int* __restrict__ eidx) {
    __shared__ int rc[NN];
    __shared__ int sd[256];
    int b = blockIdx.x, t = threadIdx.x;
    for (int i = t; i < NN; i += 256) rc[i] = 0;
    __syncthreads();
    int ebase = b * CHUNK;
#pragma unroll
    for (int j = 0; j < CHUNK / 256; j++) {
        int e = ebase + j * 256 + t;
        int d = (e < EE) ? eidx[EE + e] : -1;
        sd[t] = d;
        __syncthreads();
        if (d >= 0) {
            int rank = 0;
            for (int k = 0; k < t; k++) rank += (sd[k] == d);
            int pos = g_binBase[d] + g_chunkCnt[b * NN + d] + rc[d] + rank;
            g_perm[pos] = e;
            g_ssrc[pos] = eidx[e];
            g_sdst[pos] = d;
        }
        __syncthreads();
        if (d >= 0) atomicAdd(&rc[d], 1);
        __syncthreads();
    }
}

// ---------------- tf32 mma building blocks (templated N-tile; UNPACKED stride-264 B) ----------------
template <int NT>
__device__ __forceinline__ void compute_k16_t(const float* sA, int astr, int arow0, int k0,
                                              const float* sWb, int lane, int col0,
                                              float acc[2][NT][4]) {
    int q = lane >> 2, c = lane & 3;
#pragma unroll
    for (int ks = 0; ks < 16; ks += 8) {
        uint32_t a[2][4];
#pragma unroll
        for (int mt = 0; mt < 2; mt++) {
            const float* ap = sA + (arow0 + mt * 16 + q) * astr + k0 + ks + c;
            a[mt][0] = F2U(ap[0]);
            a[mt][2] = F2U(ap[4]);
            a[mt][1] = F2U(ap[8 * astr]);
            a[mt][3] = F2U(ap[8 * astr + 4]);
        }
#pragma unroll
        for (int nt = 0; nt < NT; nt++) {
            const float* bp = sWb + (ks + c) * 264 + col0 + nt * 8 + q;
            uint32_t b0 = F2U(bp[0]);
            uint32_t b1 = F2U(bp[4 * 264]);
            mma8(acc[0][nt], a[0][0], a[0][1], a[0][2], a[0][3], b0, b1);
            mma8(acc[1][nt], a[1][0], a[1][1], a[1][2], a[1][3], b0, b1);
        }
    }
}

template <int NT>
__device__ __forceinline__ void mma_loop_t(const float* sA, int astr, float* sW, uint32_t sWu,
                                           const float* __restrict__ Wg, int wst,
                                           int tid, int lane, int arow0, int col0,
                                           float acc[2][NT][4]) {
#pragma unroll
    for (int mt = 0; mt < 2; mt++)
#pragma unroll
        for (int nt = 0; nt < NT; nt++)
#pragma unroll
            for (int z = 0; z < 4; z++) acc[mt][nt][z] = 0.f;
    {
#pragma unroll
        for (int qq = 0; qq < 4; qq++) {
            int v = qq * 256 + tid, row = v >> 6, c4 = (v & 63) * 4;
            cp16(sWu + (uint32_t)((row * 264 + c4) * 4), Wg + row * wst + c4);
        }
        cp_commit();
    }
    for (int t = 0; t < 16; t++) {
        if (t + 1 < 16) {
            const float* src = Wg + (t + 1) * 16 * wst;
            uint32_t dbase = sWu + (uint32_t)((((t + 1) & 1) * 16 * 264) * 4);
#pragma unroll
            for (int qq = 0; qq < 4; qq++) {
                int v = qq * 256 + tid, row = v >> 6, c4 = (v & 63) * 4;
                cp16(dbase + (uint32_t)((row * 264 + c4) * 4), src + row * wst + c4);
            }
            cp_commit();
            cp_wait1();
        } else {
            cp_wait0();
        }
        __syncthreads();
        compute_k16_t<NT>(sA, astr, arow0, t * 16, sW + (t & 1) * 16 * 264, lane, col0, acc);
        __syncthreads();
    }
}

template <int NT>
__device__ __forceinline__ void fmma24_t(const float* sRbfA, const float* sW, int lane,
                                         int arow0, int col0, float facc[2][NT][4]) {
#pragma unroll
    for (int mt = 0; mt < 2; mt++)
#pragma unroll
        for (int nt = 0; nt < NT; nt++)
#pragma unroll
            for (int z = 0; z < 4; z++) facc[mt][nt][z] = 0.f;
    int q = lane >> 2, c = lane & 3;
#pragma unroll
    for (int ks = 0; ks < 24; ks += 8) {
        uint32_t a[2][4];
#pragma unroll
        for (int mt = 0; mt < 2; mt++) {
            const float* ap = sRbfA + (arow0 + mt * 16 + q) * 28 + ks + c;
            a[mt][0] = F2U(ap[0]);
            a[mt][2] = F2U(ap[4]);
            a[mt][1] = F2U(ap[8 * 28]);
            a[mt][3] = F2U(ap[8 * 28 + 4]);
        }
#pragma unroll
        for (int nt = 0; nt < NT; nt++) {
            const float* bp = sW + (ks + c) * 264 + col0 + nt * 8 + q;
            uint32_t b0 = F2U(bp[0]);
            uint32_t b1 = F2U(bp[4 * 264]);
            mma8(facc[0][nt], a[0][0], a[0][1], a[0][2], a[0][3], b0, b1);
            mma8(facc[1][nt], a[1][0], a[1][1], a[1][2], a[1][3], b0, b1);
        }
    }
}

// ---------------- node precompute P0/P1 (tf32 mma; A streamed from g_cat cols 0..255) ----------------
__global__ __launch_bounds__(256) void gemm_pre_kernel() {
    __shared__ float sW[2 * 16 * 264];
    __shared__ float sAt[2 * 64 * 20];
    uint32_t sWu = (uint32_t)__cvta_generic_to_shared(sW);
    uint32_t sAu = (uint32_t)__cvta_generic_to_shared(sAt);

    const float* Wg = blockIdx.y ? g_Wpre1 : g_Wpre0;
    float* P = blockIdx.y ? g_P1 : g_P0;

    int tid = threadIdx.x, lane = tid & 31, w = tid >> 5;
    int arow0 = (w & 1) * 32, col0 = (w >> 1) * 64;
    int q = lane >> 2, cc = lane & 3;
    int n0 = blockIdx.x * 64;

    float acc[2][8][4];
#pragma unroll
    for (int mt = 0; mt < 2; mt++)
#pragma unroll
        for (int nt = 0; nt < 8; nt++)
#pragma unroll
            for (int z = 0; z < 4; z++) acc[mt][nt][z] = 0.f;

    int arow = tid >> 2, ac4 = (tid & 3) * 4;
    int asrc_n = min(n0 + arow, NN - 1);

    {
#pragma unroll
        for (int qq = 0; qq < 4; qq++) {
            int v = qq * 256 + tid, row = v >> 6, c4 = (v & 63) * 4;
            cp16(sWu + (uint32_t)((row * 264 + c4) * 4), Wg + row * 256 + c4);
        }
        cp16(sAu + (uint32_t)((arow * 20 + ac4) * 4), g_cat + (size_t)asrc_n * 3328 + ac4);
        cp_commit();
    }
    const int KT = 16;
    for (int t = 0; t < KT; t++) {
        if (t + 1 < KT) {
            int k0 = (t + 1) * 16;
            const float* wsrc = Wg + (size_t)k0 * 256;
            uint32_t wb = sWu + (uint32_t)((((t + 1) & 1) * 16 * 264) * 4);
            uint32_t ab = sAu + (uint32_t)((((t + 1) & 1) * 64 * 20) * 4);
#pragma unroll
            for (int qq = 0; qq < 4; qq++) {
                int v = qq * 256 + tid, row = v >> 6, c4 = (v & 63) * 4;
                cp16(wb + (uint32_t)((row * 264 + c4) * 4), wsrc + row * 256 + c4);
            }
            cp16(ab + (uint32_t)((arow * 20 + ac4) * 4),
                 g_cat + (size_t)asrc_n * 3328 + k0 + ac4);
            cp_commit();
            cp_wait1();
        } else {
            cp_wait0();
        }
        __syncthreads();
        compute_k16_t<8>(sAt + (t & 1) * 64 * 20, 20, arow0, 0, sW + (t & 1) * 16 * 264,
                         lane, col0, acc);
        __syncthreads();
    }

#pragma unroll
    for (int mt = 0; mt < 2; mt++)
#pragma unroll
        for (int h = 0; h < 2; h++) {
            int r = arow0 + mt * 16 + q + h * 8;
            int n = n0 + r;
            if (n < NN) {
#pragma unroll
                for (int nt = 0; nt < 8; nt++) {
                    int c = col0 + nt * 8 + cc * 2;
                    float2 o;
                    o.x = acc[mt][nt][h * 2 + 0];
                    o.y = acc[mt][nt][h * 2 + 1];
                    *(float2*)&P[(size_t)n * 256 + c] = o;
                }
            }
        }
}

// ---------------- fused edge kernel (256 threads; 32 edges/CTA; 2 CTAs/SM) ----------------
// smem floats: sA 32x260 | sM 32x260 | sW 2x16x264 | sRbfA 32x28 | sEv 96 | src/dst/perm 96 ints
#define EDGE_SMEM_FLOATS (8320 + 8320 + 8448 + 896 + 96 + 96)
#define EDGE_SMEM_BYTES (EDGE_SMEM_FLOATS * 4)

__global__ __launch_bounds__(256, 2) void edge_kernel(
    const float* __restrict__ x, const float* __restrict__ edge_rbf,
    const float* __restrict__ edge_vec,
    const float* __restrict__ bemb, const float* __restrict__ bpre,
    const float* __restrict__ bs1, const float* __restrict__ bs2,
    float* __restrict__ out_v) {
    extern __shared__ float sm[];
    float* sA    = sm;
    float* sM    = sm + 8320;
    float* sW    = sm + 16640;
    float* sRbfA = sm + 25088;
    float* sEv   = sm + 25984;
    int* sSrc  = (int*)(sm + 26080);
    int* sDst  = sSrc + 32;
    int* sPerm = sDst + 32;
    uint32_t sWu = (uint32_t)__cvta_generic_to_shared(sW);

    int tid = threadIdx.x, lane = tid & 31, w = tid >> 5;
    const int arow0 = 0;
    int col0 = w * 32;                    // warp tile 32x32
    int q = lane >> 2, cc = lane & 3;
    int e0 = blockIdx.x * TE;

    if (tid < TE) {
        sSrc[tid]  = g_ssrc[e0 + tid];
        sDst[tid]  = g_sdst[e0 + tid];
        sPerm[tid] = g_perm[e0 + tid];
    }
    __syncthreads();

    // rbf gather (via perm), tf32-rounded, padded to 24 cols (stride 28): 640 elems
#pragma unroll
    for (int j = 0; j < 3; j++) {
        int i = tid + j * 256;
        if (i < TE * RR) {
            int e = i / 20, k = i - e * 20;
            sRbfA[e * 28 + k] = tf32r(edge_rbf[(size_t)sPerm[e] * RR + k]);
        }
    }
    if (tid < 128) { int e = tid >> 2, k = 20 + (tid & 3); sRbfA[e * 28 + k] = 0.f; }
    if (tid < 96) {
        int e = tid / 3, comp = tid - e * 3;
        sEv[tid] = edge_vec[(size_t)sPerm[e] * 3 + comp];
    }
    // Wemb -> sW rows 0..19, zero rows 20..23
#pragma unroll
    for (int j = 0; j < 5; j++) {
        int v = tid + j * 256, row = v >> 6, c4 = (v & 63) * 4;
        *(float4*)&sW[row * 264 + c4] = *(const float4*)&g_Wemb[row * 256 + c4];
    }
    { int row = 20 + (tid >> 6), c4 = (tid & 63) * 4;
      *(float4*)&sW[row * 264 + c4] = make_float4(0.f, 0.f, 0.f, 0.f); }
    __syncthreads();

    // prefill sM = P0[src] + P1[dst] + bpre (2048 float4s)
#pragma unroll
    for (int j = 0; j < 8; j++) {
        int f = (tid + j * 256) * 4;
        int r = f >> 8, c = f & 255;
        int s = sSrc[r], d = sDst[r];
        float4 p0 = *(const float4*)&g_P0[s * 256 + c];
        float4 p1 = *(const float4*)&g_P1[d * 256 + c];
        float4 bb = *(const float4*)&bpre[c];
        *(float4*)&sM[r * 260 + c] =
            make_float4(p0.x + p1.x + bb.x, p0.y + p1.y + bb.y,
                        p0.z + p1.z + bb.z, p0.w + p1.w + bb.w);
    }

    float acc[2][4][4];

    // ---- stage 1: sA = round(relu(rbf@Wemb + bemb)) ----
    fmma24_t<4>(sRbfA, sW, lane, arow0, col0, acc);
    {
        float2 bias[4];
#pragma unroll
        for (int nt = 0; nt < 4; nt++) bias[nt] = *(const float2*)&bemb[col0 + nt * 8 + cc * 2];
#pragma unroll
        for (int mt = 0; mt < 2; mt++)
#pragma unroll
            for (int h = 0; h < 2; h++) {
                int r = arow0 + mt * 16 + q + h * 8;
#pragma unroll
                for (int nt = 0; nt < 4; nt++) {
                    int c = col0 + nt * 8 + cc * 2;
                    sA[r * 260 + c]     = tf32r(fmaxf(acc[mt][nt][h * 2 + 0] + bias[nt].x, 0.f));
                    sA[r * 260 + c + 1] = tf32r(fmaxf(acc[mt][nt][h * 2 + 1] + bias[nt].y, 0.f));
                }
            }
    }
    __syncthreads();

    // ---- stage 2: sM = round(sA@Wpre2 + sM) ----
    mma_loop_t<4>(sA, 260, sW, sWu, g_Wpre2, 256, tid, lane, arow0, col0, acc);
#pragma unroll
    for (int mt = 0; mt < 2; mt++)
#pragma unroll
        for (int h = 0; h < 2; h++) {
            int r = arow0 + mt * 16 + q + h * 8;
#pragma unroll
            for (int nt = 0; nt < 4; nt++) {
                int c = col0 + nt * 8 + cc * 2;
                float* p = &sM[r * 260 + c];
                p[0] = tf32r(acc[mt][nt][h * 2 + 0] + p[0]);
                p[1] = tf32r(acc[mt][nt][h * 2 + 1] + p[1]);
            }
        }
    __syncthreads();

    // ---- stage 3: sA = round(silu(sM@Ws1 + bs1)) ----
    mma_loop_t<4>(sM, 260, sW, sWu, g_Ws1, 256, tid, lane, arow0, col0, acc);
    {
        float2 bias[4];
#pragma unroll
        for (int nt = 0; nt < 4; nt++) bias[nt] = *(const float2*)&bs1[col0 + nt * 8 + cc * 2];
#pragma unroll
        for (int mt = 0; mt < 2; mt++)
#pragma unroll
            for (int h = 0; h < 2; h++) {
                int r = arow0 + mt * 16 + q + h * 8;
#pragma unroll
                for (int nt = 0; nt < 4; nt++) {
                    int c = col0 + nt * 8 + cc * 2;
                    float m0 = acc[mt][nt][h * 2 + 0] + bias[nt].x;
                    float m1 = acc[mt][nt][h * 2 + 1] + bias[nt].y;
                    sA[r * 260 + c]     = tf32r(__fdividef(m0, 1.f + __expf(-m0)));
                    sA[r * 260 + c + 1] = tf32r(__fdividef(m1, 1.f + __expf(-m1)));
                }
            }
    }
    __syncthreads();

    // ---- stage 4: three 256-col chunks of Ws2, fused with f = rbf@Wlin ----
    for (int ch = 0; ch < 3; ch++) {
        mma_loop_t<4>(sA, 260, sW, sWu, g_Ws2 + ch * 256, 768, tid, lane, arow0, col0, acc);
        // Wlin chunk into sW rows 0..19, zero rows 20..23
#pragma unroll
        for (int j = 0; j < 5; j++) {
            int v = tid + j * 256, row = v >> 6, c4 = (v & 63) * 4;
            *(float4*)&sW[row * 264 + c4] = *(const float4*)&g_Wlin[row * 768 + ch * 256 + c4];
        }
        { int row = 20 + (tid >> 6), c4 = (tid & 63) * 4;
          *(float4*)&sW[row * 264 + c4] = make_float4(0.f, 0.f, 0.f, 0.f); }
        __syncthreads();
        float facc[2][4][4];
        fmma24_t<4>(sRbfA, sW, lane, arow0, col0, facc);
        float2 bias[4];
#pragma unroll
        for (int nt = 0; nt < 4; nt++)
            bias[nt] = *(const float2*)&bs2[ch * 256 + col0 + nt * 8 + cc * 2];

        if (ch == 0) {
            // g_state -> sM
#pragma unroll
            for (int mt = 0; mt < 2; mt++)
#pragma unroll
                for (int h = 0; h < 2; h++) {
                    int r = arow0 + mt * 16 + q + h * 8;
#pragma unroll
                    for (int nt = 0; nt < 4; nt++) {
                        int c = col0 + nt * 8 + cc * 2;
                        sM[r * 260 + c]     = (acc[mt][nt][h * 2 + 0] + bias[nt].x) * facc[mt][nt][h * 2 + 0];
                        sM[r * 260 + c + 1] = (acc[mt][nt][h * 2 + 1] + bias[nt].y) * facc[mt][nt][h * 2 + 1];
                    }
                }
            __syncthreads();
        } else if (ch == 1) {
            // g_edge: segmented mv scatter, two 128-col passes using sW as ge scratch
            __syncthreads();
            for (int half = 0; half < 2; half++) {
                int colbase = half * 128;
                if (col0 >= colbase && col0 < colbase + 128) {
#pragma unroll
                    for (int mt = 0; mt < 2; mt++)
#pragma unroll
                        for (int h = 0; h < 2; h++) {
                            int r = arow0 + mt * 16 + q + h * 8;
#pragma unroll
                            for (int nt = 0; nt < 4; nt++) {
                                int c = col0 + nt * 8 + cc * 2;
                                float g0 = (acc[mt][nt][h * 2 + 0] + bias[nt].x) * facc[mt][nt][h * 2 + 0];
                                float g1 = (acc[mt][nt][h * 2 + 1] + bias[nt].y) * facc[mt][nt][h * 2 + 1];
                                int off = c - colbase;
                                sW[r * 132 + off]     = g0;
                                sW[r * 132 + off + 1] = g1;
                            }
                        }
                }
                __syncthreads();
                if (tid < 128) {
                    int c = colbase + tid;
                    int dprev = sDst[0];
                    float Sgs = 0.f, S0 = 0.f, S1 = 0.f, S2 = 0.f;
                    for (int r = 0; r < TE; r++) {
                        int d = sDst[r];
                        if (d != dprev) {
                            float xv = x[(size_t)dprev * 256 + c];
                            float* vb = out_v + (size_t)dprev * 768 + c;
                            atomicAdd(vb,       fmaf(xv, Sgs, S0));
                            atomicAdd(vb + 256, fmaf(xv, Sgs, S1));
                            atomicAdd(vb + 512, fmaf(xv, Sgs, S2));
                            Sgs = S0 = S1 = S2 = 0.f;
                            dprev = d;
                        }
                        float gs = sM[r * 260 + c];
                        float ge = sW[r * 132 + tid];
                        Sgs += gs;
                        S0 = fmaf(sEv[r * 3 + 0], ge, S0);
                        S1 = fmaf(sEv[r * 3 + 1], ge, S1);
                        S2 = fmaf(sEv[r * 3 + 2], ge, S2);
                    }
                    float xv = x[(size_t)dprev * 256 + c];
                    float* vb = out_v + (size_t)dprev * 768 + c;
                    atomicAdd(vb,       fmaf(xv, Sgs, S0));
                    atomicAdd(vb + 256, fmaf(xv, Sgs, S1));
                    atomicAdd(vb + 512, fmaf(xv, Sgs, S2));
                }
                __syncthreads();
            }
        } else {
            // ms stats: write to sA (free after final GEMM), segmented scan + coalesced flush
#pragma unroll
            for (int mt = 0; mt < 2; mt++)
#pragma unroll
                for (int h = 0; h < 2; h++) {
                    int r = arow0 + mt * 16 + q + h * 8;
#pragma unroll
                    for (int nt = 0; nt < 4; nt++) {
                        int c = col0 + nt * 8 + cc * 2;
                        sA[r * 260 + c]     = (acc[mt][nt][h * 2 + 0] + bias[nt].x) * facc[mt][nt][h * 2 + 0];
                        sA[r * 260 + c + 1] = (acc[mt][nt][h * 2 + 1] + bias[nt].y) * facc[mt][nt][h * 2 + 1];
                    }
                }
            __syncthreads();
            {
                int c = tid;
                int dprev = sDst[0];
                float S = 0.f, SS = 0.f;
                float mn = __int_as_float(0x7f800000), mx = __int_as_float(0xff800000);
                for (int r = 0; r < TE; r++) {
                    int d = sDst[r];
                    if (d != dprev) {
                        int a = dprev * 256 + c;
                        atomicAdd(&g_sum[a], S);
                        atomicAdd(&g_sumsq[a], SS);
                        atomicMaxF(&g_maxb[a], mx);
                        atomicMinF(&g_minb[a], mn);
                        S = SS = 0.f;
                        mn = __int_as_float(0x7f800000);
                        mx = __int_as_float(0xff800000);
                        dprev = d;
                    }
                    float v = sA[r * 260 + c];
                    S += v;
                    SS = fmaf(v, v, SS);
                    mn = fminf(mn, v);
                    mx = fmaxf(mx, v);
                }
                int a = dprev * 256 + c;
                atomicAdd(&g_sum[a], S);
                atomicAdd(&g_sumsq[a], SS);
                atomicMaxF(&g_maxb[a], mx);
                atomicMinF(&g_minb[a], mn);
            }
        }
    }
}

// ---------------- aggs -> g_cat (rounded) ----------------
__global__ void agg_kernel() {
    int idx = blockIdx.x * 256 + threadIdx.x;
    if (idx >= NN * FF) return;
    int n = idx >> 8;
    int c = idx & 255;
    float deg  = g_deg[n];
    float degc = fmaxf(deg, 1.f);
    float mean = g_sum[idx] / degc;
    float msq  = g_sumsq[idx] / degc;
    float stdv = sqrtf(fmaxf(msq - mean * mean, 0.f) + 1e-5f);
    float mn = (deg > 0.f) ? g_minb[idx] : 0.f;
    float mx = (deg > 0.f) ? g_maxb[idx] : 0.f;
    float avg  = g_avglog;
    float logd = log1pf(deg);
    float s1 = logd / avg;
    float s2 = avg / log1pf(degc);
    float* base = g_cat + (size_t)n * 3328 + 256 + c;
    base[0 * FF]  = tf32r(mean);      base[1 * FF]  = tf32r(mn);
    base[2 * FF]  = tf32r(mx);        base[3 * FF]  = tf32r(stdv);
    base[4 * FF]  = tf32r(mean * s1); base[5 * FF]  = tf32r(mn * s1);
    base[6 * FF]  = tf32r(mx * s1);   base[7 * FF]  = tf32r(stdv * s1);
    base[8 * FF]  = tf32r(mean * s2); base[9 * FF]  = tf32r(mn * s2);
    base[10 * FF] = tf32r(mx * s2);   base[11 * FF] = tf32r(stdv * s2);
}

// ---------------- post GEMM: out_x = x + g_cat @ Wpost + bpost (tf32 mma) ----------------
__global__ __launch_bounds__(256) void gemm_post_kernel(const float* __restrict__ x,
                                                        const float* __restrict__ bpost,
                                                        float* __restrict__ out_x) {
    __shared__ float sW[2 * 16 * 264];
    __shared__ float sAt[2 * 64 * 20];
    uint32_t sWu = (uint32_t)__cvta_generic_to_shared(sW);
    uint32_t sAu = (uint32_t)__cvta_generic_to_shared(sAt);

    int tid = threadIdx.x, lane = tid & 31, w = tid >> 5;
    int arow0 = (w & 1) * 32, col0 = (w >> 1) * 64;
    int q = lane >> 2, cc = lane & 3;
    int n0 = blockIdx.x * 64;

    float acc[2][8][4];
#pragma unroll
    for (int mt = 0; mt < 2; mt++)
#pragma unroll
        for (int nt = 0; nt < 8; nt++)
#pragma unroll
            for (int z = 0; z < 4; z++) acc[mt][nt][z] = 0.f;

    int arow = tid >> 2, ac4 = (tid & 3) * 4;
    int asrc_n = min(n0 + arow, NN - 1);

    {
#pragma unroll
        for (int qq = 0; qq < 4; qq++) {
            int v = qq * 256 + tid, row = v >> 6, c4 = (v & 63) * 4;
            cp16(sWu + (uint32_t)((row * 264 + c4) * 4), g_Wpost + row * 256 + c4);
        }
        cp16(sAu + (uint32_t)((arow * 20 + ac4) * 4), g_cat + (size_t)asrc_n * 3328 + ac4);
        cp_commit();
    }
    const int KT = 3328 / 16;
    for (int t = 0; t < KT; t++) {
        if (t + 1 < KT) {
            int k0 = (t + 1) * 16;
            const float* wsrc = g_Wpost + (size_t)k0 * 256;
            uint32_t wb = sWu + (uint32_t)((((t + 1) & 1) * 16 * 264) * 4);
            uint32_t ab = sAu + (uint32_t)((((t + 1) & 1) * 64 * 20) * 4);
#pragma unroll
            for (int qq = 0; qq < 4; qq++) {
                int v = qq * 256 + tid, row = v >> 6, c4 = (v & 63) * 4;
                cp16(wb + (uint32_t)((row * 264 + c4) * 4), wsrc + row * 256 + c4);
            }
            cp16(ab + (uint32_t)((arow * 20 + ac4) * 4),
                 g_cat + (size_t)asrc_n * 3328 + k0 + ac4);
            cp_commit();
            cp_wait1();
        } else {
            cp_wait0();
        }
        __syncthreads();
        compute_k16_t<8>(sAt + (t & 1) * 64 * 20, 20, arow0, 0, sW + (t & 1) * 16 * 264,
                         lane, col0, acc);
        __syncthreads();
    }

#pragma unroll
    for (int mt = 0; mt < 2; mt++)
#pragma unroll
        for (int h = 0; h < 2; h++) {
            int r = arow0 + mt * 16 + q + h * 8;
            int n = n0 + r;
            if (n < NN) {
#pragma unroll
                for (int nt = 0; nt < 8; nt++) {
                    int c = col0 + nt * 8 + cc * 2;
                    float2 xv = *(const float2*)&x[(size_t)n * 256 + c];
                    float2 bb = *(const float2*)&bpost[c];
                    float2 o;
                    o.x = xv.x + acc[mt][nt][h * 2 + 0] + bb.x;
                    o.y = xv.y + acc[mt][nt][h * 2 + 1] + bb.y;
                    *(float2*)&out_x[(size_t)n * 256 + c] = o;
                }
            }
        }
}

// ---------------- launch ----------------
extern "C" void kernel_launch(void* const* d_in, const int* in_sizes, int n_in,
                              void* d_out, int out_size) {
    const float* x        = (const float*)d_in[0];
    const float* v        = (const float*)d_in[1];
    const float* edge_rbf = (const float*)d_in[2];
    const float* edge_vec = (const float*)d_in[3];
    const float* Wemb     = (const float*)d_in[4];
    const float* bemb     = (const float*)d_in[5];
    const float* Wpre     = (const float*)d_in[6];
    const float* bpre     = (const float*)d_in[7];
    const float* Ws1      = (const float*)d_in[8];
    const float* bs1      = (const float*)d_in[9];
    const float* Ws2      = (const float*)d_in[10];
    const float* bs2      = (const float*)d_in[11];
    const float* Wlin     = (const float*)d_in[12];
    const float* Wpost    = (const float*)d_in[13];
    const float* bpost    = (const float*)d_in[14];
    const int*   eidx     = (const int*)d_in[15];

    float* out_x = (float*)d_out;
    float* out_v = out_x + (size_t)NN * FF;

    cudaFuncSetAttribute(edge_kernel, cudaFuncAttributeMaxDynamicSharedMemorySize,
                         EDGE_SMEM_BYTES);

    cudaMemcpyAsync(out_v, v, (size_t)NN * 3 * FF * sizeof(float), cudaMemcpyDeviceToDevice);

    cvt_kernel<<<(3328 * FF + 255) / 256, 256>>>(Wemb, Wpre, Ws1, Ws2, Wlin, Wpost);
    init_kernel<<<(NN * FF + 255) / 256, 256>>>(x);
    hist_kernel<<<NCHUNK, 256>>>(eidx);
    scanA_kernel<<<(NN + 255) / 256, 256>>>();
    scanB_kernel<<<1, 256>>>();
    scatter_kernel<<<NCHUNK, 256>>>(eidx);
    gemm_pre_kernel<<<dim3((NN + 63) / 64, 2), 256>>>();
    edge_kernel<<<EE / TE, 256, EDGE_SMEM_BYTES>>>(x, edge_rbf, edge_vec,
                                                   bemb, bpre, bs1, bs2, out_v);
    agg_kernel<<<(NN * FF + 255) / 256, 256>>>();
    gemm_post_kernel<<<(NN + 63) / 64, 256>>>(x, bpost, out_x);
}

// round 16
// speedup vs baseline: 1.2089x; 1.0113x over previous
#include <cuda_runtime.h>
#include <math.h>
#include <stdint.h>

#define NN 10000
#define EE 160000
#define FF 256
#define RR 20
#define TE 32
#define CHUNK 2048
#define NCHUNK 79   // ceil(EE / CHUNK)

// ---------------- device scratch ----------------
__device__ float g_P0[NN * FF];
__device__ float g_P1[NN * FF];
__device__ float g_sum[NN * FF];
__device__ float g_sumsq[NN * FF];
__device__ float g_minb[NN * FF];
__device__ float g_maxb[NN * FF];
__device__ float g_deg[NN];
__device__ float g_avglog;
__device__ float g_cat[NN * 3328];
// sort scratch
__device__ int g_chunkCnt[NCHUNK * NN];
__device__ int g_binCnt[NN];
__device__ int g_binBase[NN];
__device__ int g_perm[EE];
__device__ int g_ssrc[EE];
__device__ int g_sdst[EE];
// tf32-rounded weight copies (row-major, unpacked)
__device__ float g_Wemb[RR * FF];
__device__ float g_Wpre0[FF * FF];
__device__ float g_Wpre1[FF * FF];
__device__ float g_Wpre2[FF * FF];
__device__ float g_Ws1[FF * FF];
__device__ float g_Ws2[FF * 3 * FF];
__device__ float g_Wlin[RR * 3 * FF];
__device__ float g_Wpost[3328 * FF];

// ---------------- helpers ----------------
__device__ __forceinline__ float tf32r(float x) {
    uint32_t u;
    asm("cvt.rna.tf32.f32 %0, %1;" : "=r"(u) : "f"(x));
    return __uint_as_float(u);
}
__device__ __forceinline__ uint32_t F2U(float f) { return __float_as_uint(f); }

__device__ __forceinline__ void mma8(float c[4], uint32_t a0, uint32_t a1, uint32_t a2,
                                     uint32_t a3, uint32_t b0, uint32_t b1) {
    asm volatile(
        "mma.sync.aligned.m16n8k8.row.col.f32.tf32.tf32.f32 "
        "{%0,%1,%2,%3},{%4,%5,%6,%7},{%8,%9},{%0,%1,%2,%3};"
        : "+f"(c[0]), "+f"(c[1]), "+f"(c[2]), "+f"(c[3])
        : "r"(a0), "r"(a1), "r"(a2), "r"(a3), "r"(b0), "r"(b1));
}

__device__ __forceinline__ void cp16(uint32_t saddr, const void* g) {
    asm volatile("cp.async.ca.shared.global [%0], [%1], 16;" :: "r"(saddr), "l"(g));
}
__device__ __forceinline__ void cp_commit() { asm volatile("cp.async.commit_group;"); }
__device__ __forceinline__ void cp_wait1()  { asm volatile("cp.async.wait_group 1;"); }
__device__ __forceinline__ void cp_wait0()  { asm volatile("cp.async.wait_group 0;"); }

__device__ __forceinline__ void atomicMaxF(float* p, float v) {
    if (v >= 0.f) atomicMax((int*)p, __float_as_int(v));
    else          atomicMin((unsigned int*)p, __float_as_uint(v));
}
__device__ __forceinline__ void atomicMinF(float* p, float v) {
    if (v >= 0.f) atomicMin((int*)p, __float_as_int(v));
    else          atomicMax((unsigned int*)p, __float_as_uint(v));
}

// ---------------- weight conversion ----------------
__global__ void cvt_kernel(const float* __restrict__ Wemb, const float* __restrict__ Wpre,
                           const float* __restrict__ Ws1, const float* __restrict__ Ws2,
                           const float* __restrict__ Wlin, const float* __restrict__ Wpost) {
    int i = blockIdx.x * 256 + threadIdx.x;
    if (i < RR * FF)     g_Wemb[i]  = tf32r(Wemb[i]);
    if (i < FF * FF) {
        g_Wpre0[i] = tf32r(Wpre[i]);
        g_Wpre1[i] = tf32r(Wpre[FF * FF + i]);
        g_Wpre2[i] = tf32r(Wpre[2 * FF * FF + i]);
        g_Ws1[i]   = tf32r(Ws1[i]);
    }
    if (i < FF * 3 * FF) g_Ws2[i]   = tf32r(Ws2[i]);
    if (i < RR * 3 * FF) g_Wlin[i]  = tf32r(Wlin[i]);
    if (i < 3328 * FF)   g_Wpost[i] = tf32r(Wpost[i]);
}

// ---------------- init ----------------
__global__ void init_kernel(const float* __restrict__ x) {
    int i = blockIdx.x * 256 + threadIdx.x;
    if (i < NN * FF) {
        g_sum[i]   = 0.f;
        g_sumsq[i] = 0.f;
        g_minb[i]  = __int_as_float(0x7f800000);
        g_maxb[i]  = __int_as_float(0xff800000);
        int n = i >> 8, c = i & 255;
        g_cat[n * 3328 + c] = tf32r(x[i]);
    }
}

// ---------------- sort: per-chunk histogram (2048-edge chunks) ----------------
__global__ __launch_bounds__(256) void hist_kernel(const int* __restrict__ eidx) {
    __shared__ int shist[NN];
    int b = blockIdx.x, t = threadIdx.x;
    for (int i = t; i < NN; i += 256) shist[i] = 0;
    __syncthreads();
    int ebase = b * CHUNK;
#pragma unroll
    for (int j = 0; j < CHUNK / 256; j++) {
        int e = ebase + j * 256 + t;
        if (e < EE) atomicAdd(&shist[eidx[EE + e]], 1);
    }
    __syncthreads();
    for (int i = t; i < NN; i += 256) g_chunkCnt[b * NN + i] = shist[i];
}

// ---------------- sort: per-bin scan over chunks ----------------
__global__ void scanA_kernel() {
    int d = blockIdx.x * 256 + threadIdx.x;
    if (d >= NN) return;
    int run = 0;
    for (int b = 0; b < NCHUNK; b++) {
        int idx = b * NN + d;
        int t = g_chunkCnt[idx];
        g_chunkCnt[idx] = run;
        run += t;
    }
    g_binCnt[d] = run;
    g_deg[d] = (float)run;
}

// ---------------- sort: exclusive scan over bins + avg_log (single block) ----------------
__global__ void scanB_kernel() {
    __shared__ int sp[256];
    __shared__ float sf[256];
    int t = threadIdx.x;
    int lo = t * 40, hi = min(lo + 40, NN);
    int s = 0;
    float ls = 0.f;
    for (int i = lo; i < hi; i++) {
        int c = g_binCnt[i];
        s += c;
        ls += log1pf((float)c);
    }
    sp[t] = s;
    sf[t] = ls;
    __syncthreads();
    for (int off = 1; off < 256; off <<= 1) {
        int v = (t >= off) ? sp[t - off] : 0;
        __syncthreads();
        sp[t] += v;
        __syncthreads();
    }
    int base = (t > 0) ? sp[t - 1] : 0;
    for (int i = lo; i < hi; i++) {
        int c = g_binCnt[i];
        g_binBase[i] = base;
        base += c;
    }
    for (int off = 128; off > 0; off >>= 1) {
        if (t < off) sf[t] += sf[t + off];
        __syncthreads();
    }
    if (t == 0) g_avglog = sf[0] / (float)NN;
}

// ---------------- sort: stable scatter (8 rounds of 256 per chunk) ----------------
__global__ __launch_bounds__(256) void scatter_kernel(const int* __restrict__ eidx) {
    __shared__ int rc[NN];
    __shared__ int sd[256];
    int b = blockIdx.x, t = threadIdx.x;
    for (int i = t; i < NN; i += 256) rc[i] = 0;
    __syncthreads();
    int ebase = b * CHUNK;
#pragma unroll
    for (int j = 0; j < CHUNK / 256; j++) {
        int e = ebase + j * 256 + t;
        int d = (e < EE) ? eidx[EE + e] : -1;
        sd[t] = d;
        __syncthreads();
        if (d >= 0) {
            int rank = 0;
            for (int k = 0; k < t; k++) rank += (sd[k] == d);
            int pos = g_binBase[d] + g_chunkCnt[b * NN + d] + rc[d] + rank;
            g_perm[pos] = e;
            g_ssrc[pos] = eidx[e];
            g_sdst[pos] = d;
        }
        __syncthreads();
        if (d >= 0) atomicAdd(&rc[d], 1);
        __syncthreads();
    }
}

// ---------------- tf32 mma building blocks (templated N-tile; UNPACKED stride-264 B) ----------------
template <int NT>
__device__ __forceinline__ void compute_k16_t(const float* sA, int astr, int arow0, int k0,
                                              const float* sWb, int lane, int col0,
                                              float acc[2][NT][4]) {
    int q = lane >> 2, c = lane & 3;
#pragma unroll
    for (int ks = 0; ks < 16; ks += 8) {
        uint32_t a[2][4];
#pragma unroll
        for (int mt = 0; mt < 2; mt++) {
            const float* ap = sA + (arow0 + mt * 16 + q) * astr + k0 + ks + c;
            a[mt][0] = F2U(ap[0]);
            a[mt][2] = F2U(ap[4]);
            a[mt][1] = F2U(ap[8 * astr]);
            a[mt][3] = F2U(ap[8 * astr + 4]);
        }
#pragma unroll
        for (int nt = 0; nt < NT; nt++) {
            const float* bp = sWb + (ks + c) * 264 + col0 + nt * 8 + q;
            uint32_t b0 = F2U(bp[0]);
            uint32_t b1 = F2U(bp[4 * 264]);
            mma8(acc[0][nt], a[0][0], a[0][1], a[0][2], a[0][3], b0, b1);
            mma8(acc[1][nt], a[1][0], a[1][1], a[1][2], a[1][3], b0, b1);
        }
    }
}

template <int NT>
__device__ __forceinline__ void mma_loop_t(const float* sA, int astr, float* sW, uint32_t sWu,
                                           const float* __restrict__ Wg, int wst,
                                           int tid, int lane, int arow0, int col0,
                                           float acc[2][NT][4]) {
#pragma unroll
    for (int mt = 0; mt < 2; mt++)
#pragma unroll
        for (int nt = 0; nt < NT; nt++)
#pragma unroll
            for (int z = 0; z < 4; z++) acc[mt][nt][z] = 0.f;
    {
#pragma unroll
        for (int qq = 0; qq < 4; qq++) {
            int v = qq * 256 + tid, row = v >> 6, c4 = (v & 63) * 4;
            cp16(sWu + (uint32_t)((row * 264 + c4) * 4), Wg + row * wst + c4);
        }
        cp_commit();
    }
    for (int t = 0; t < 16; t++) {
        if (t + 1 < 16) {
            const float* src = Wg + (t + 1) * 16 * wst;
            uint32_t dbase = sWu + (uint32_t)((((t + 1) & 1) * 16 * 264) * 4);
#pragma unroll
            for (int qq = 0; qq < 4; qq++) {
                int v = qq * 256 + tid, row = v >> 6, c4 = (v & 63) * 4;
                cp16(dbase + (uint32_t)((row * 264 + c4) * 4), src + row * wst + c4);
            }
            cp_commit();
            cp_wait1();
        } else {
            cp_wait0();
        }
        __syncthreads();
        compute_k16_t<NT>(sA, astr, arow0, t * 16, sW + (t & 1) * 16 * 264, lane, col0, acc);
        __syncthreads();
    }
}

template <int NT>
__device__ __forceinline__ void fmma24_t(const float* sRbfA, const float* sW, int lane,
                                         int arow0, int col0, float facc[2][NT][4]) {
#pragma unroll
    for (int mt = 0; mt < 2; mt++)
#pragma unroll
        for (int nt = 0; nt < NT; nt++)
#pragma unroll
            for (int z = 0; z < 4; z++) facc[mt][nt][z] = 0.f;
    int q = lane >> 2, c = lane & 3;
#pragma unroll
    for (int ks = 0; ks < 24; ks += 8) {
        uint32_t a[2][4];
#pragma unroll
        for (int mt = 0; mt < 2; mt++) {
            const float* ap = sRbfA + (arow0 + mt * 16 + q) * 28 + ks + c;
            a[mt][0] = F2U(ap[0]);
            a[mt][2] = F2U(ap[4]);
            a[mt][1] = F2U(ap[8 * 28]);
            a[mt][3] = F2U(ap[8 * 28 + 4]);
        }
#pragma unroll
        for (int nt = 0; nt < NT; nt++) {
            const float* bp = sW + (ks + c) * 264 + col0 + nt * 8 + q;
            uint32_t b0 = F2U(bp[0]);
            uint32_t b1 = F2U(bp[4 * 264]);
            mma8(facc[0][nt], a[0][0], a[0][1], a[0][2], a[0][3], b0, b1);
            mma8(facc[1][nt], a[1][0], a[1][1], a[1][2], a[1][3], b0, b1);
        }
    }
}

// ---------------- node precompute P0/P1 (tf32 mma; A streamed from g_cat cols 0..255) ----------------
__global__ __launch_bounds__(256) void gemm_pre_kernel() {
    __shared__ float sW[2 * 16 * 264];
    __shared__ float sAt[2 * 64 * 20];
    uint32_t sWu = (uint32_t)__cvta_generic_to_shared(sW);
    uint32_t sAu = (uint32_t)__cvta_generic_to_shared(sAt);

    const float* Wg = blockIdx.y ? g_Wpre1 : g_Wpre0;
    float* P = blockIdx.y ? g_P1 : g_P0;

    int tid = threadIdx.x, lane = tid & 31, w = tid >> 5;
    int arow0 = (w & 1) * 32, col0 = (w >> 1) * 64;
    int q = lane >> 2, cc = lane & 3;
    int n0 = blockIdx.x * 64;

    float acc[2][8][4];
#pragma unroll
    for (int mt = 0; mt < 2; mt++)
#pragma unroll
        for (int nt = 0; nt < 8; nt++)
#pragma unroll
            for (int z = 0; z < 4; z++) acc[mt][nt][z] = 0.f;

    int arow = tid >> 2, ac4 = (tid & 3) * 4;
    int asrc_n = min(n0 + arow, NN - 1);

    {
#pragma unroll
        for (int qq = 0; qq < 4; qq++) {
            int v = qq * 256 + tid, row = v >> 6, c4 = (v & 63) * 4;
            cp16(sWu + (uint32_t)((row * 264 + c4) * 4), Wg + row * 256 + c4);
        }
        cp16(sAu + (uint32_t)((arow * 20 + ac4) * 4), g_cat + (size_t)asrc_n * 3328 + ac4);
        cp_commit();
    }
    const int KT = 16;
    for (int t = 0; t < KT; t++) {
        if (t + 1 < KT) {
            int k0 = (t + 1) * 16;
            const float* wsrc = Wg + (size_t)k0 * 256;
            uint32_t wb = sWu + (uint32_t)((((t + 1) & 1) * 16 * 264) * 4);
            uint32_t ab = sAu + (uint32_t)((((t + 1) & 1) * 64 * 20) * 4);
#pragma unroll
            for (int qq = 0; qq < 4; qq++) {
                int v = qq * 256 + tid, row = v >> 6, c4 = (v & 63) * 4;
                cp16(wb + (uint32_t)((row * 264 + c4) * 4), wsrc + row * 256 + c4);
            }
            cp16(ab + (uint32_t)((arow * 20 + ac4) * 4),
                 g_cat + (size_t)asrc_n * 3328 + k0 + ac4);
            cp_commit();
            cp_wait1();
        } else {
            cp_wait0();
        }
        __syncthreads();
        compute_k16_t<8>(sAt + (t & 1) * 64 * 20, 20, arow0, 0, sW + (t & 1) * 16 * 264,
                         lane, col0, acc);
        __syncthreads();
    }

#pragma unroll
    for (int mt = 0; mt < 2; mt++)
#pragma unroll
        for (int h = 0; h < 2; h++) {
            int r = arow0 + mt * 16 + q + h * 8;
            int n = n0 + r;
            if (n < NN) {
#pragma unroll
                for (int nt = 0; nt < 8; nt++) {
                    int c = col0 + nt * 8 + cc * 2;
                    float2 o;
                    o.x = acc[mt][nt][h * 2 + 0];
                    o.y = acc[mt][nt][h * 2 + 1];
                    *(float2*)&P[(size_t)n * 256 + c] = o;
                }
            }
        }
}

// ---------------- fused edge kernel (256 threads; 32 edges/CTA; 2 CTAs/SM) ----------------
// smem floats: sA 32x260 | sM 32x260 | sW 2x16x264 | sRbfA 32x28 | sEv 96 | src/dst/perm 96 ints
#define EDGE_SMEM_FLOATS (8320 + 8320 + 8448 + 896 + 96 + 96)
#define EDGE_SMEM_BYTES (EDGE_SMEM_FLOATS * 4)

__global__ __launch_bounds__(256, 2) void edge_kernel(
    const float* __restrict__ x, const float* __restrict__ edge_rbf,
    const float* __restrict__ edge_vec,
    const float* __restrict__ bemb, const float* __restrict__ bpre,
    const float* __restrict__ bs1, const float* __restrict__ bs2,
    float* __restrict__ out_v) {
    extern __shared__ float sm[];
    float* sA    = sm;
    float* sM    = sm + 8320;
    float* sW    = sm + 16640;
    float* sRbfA = sm + 25088;
    float* sEv   = sm + 25984;
    int* sSrc  = (int*)(sm + 26080);
    int* sDst  = sSrc + 32;
    int* sPerm = sDst + 32;
    uint32_t sWu = (uint32_t)__cvta_generic_to_shared(sW);

    int tid = threadIdx.x, lane = tid & 31, w = tid >> 5;
    const int arow0 = 0;
    int col0 = w * 32;                    // warp tile 32x32
    int q = lane >> 2, cc = lane & 3;
    int e0 = blockIdx.x * TE;

    if (tid < TE) {
        sSrc[tid]  = g_ssrc[e0 + tid];
        sDst[tid]  = g_sdst[e0 + tid];
        sPerm[tid] = g_perm[e0 + tid];
    }
    __syncthreads();

    // rbf gather (via perm), tf32-rounded, padded to 24 cols (stride 28): 640 elems
#pragma unroll
    for (int j = 0; j < 3; j++) {
        int i = tid + j * 256;
        if (i < TE * RR) {
            int e = i / 20, k = i - e * 20;
            sRbfA[e * 28 + k] = tf32r(edge_rbf[(size_t)sPerm[e] * RR + k]);
        }
    }
    if (tid < 128) { int e = tid >> 2, k = 20 + (tid & 3); sRbfA[e * 28 + k] = 0.f; }
    if (tid < 96) {
        int e = tid / 3, comp = tid - e * 3;
        sEv[tid] = edge_vec[(size_t)sPerm[e] * 3 + comp];
    }
    // Wemb -> sW rows 0..19, zero rows 20..23
#pragma unroll
    for (int j = 0; j < 5; j++) {
        int v = tid + j * 256, row = v >> 6, c4 = (v & 63) * 4;
        *(float4*)&sW[row * 264 + c4] = *(const float4*)&g_Wemb[row * 256 + c4];
    }
    { int row = 20 + (tid >> 6), c4 = (tid & 63) * 4;
      *(float4*)&sW[row * 264 + c4] = make_float4(0.f, 0.f, 0.f, 0.f); }
    __syncthreads();

    // prefill sM = P0[src] + P1[dst] + bpre (2048 float4s)
#pragma unroll
    for (int j = 0; j < 8; j++) {
        int f = (tid + j * 256) * 4;
        int r = f >> 8, c = f & 255;
        int s = sSrc[r], d = sDst[r];
        float4 p0 = *(const float4*)&g_P0[s * 256 + c];
        float4 p1 = *(const float4*)&g_P1[d * 256 + c];
        float4 bb = *(const float4*)&bpre[c];
        *(float4*)&sM[r * 260 + c] =
            make_float4(p0.x + p1.x + bb.x, p0.y + p1.y + bb.y,
                        p0.z + p1.z + bb.z, p0.w + p1.w + bb.w);
    }

    float acc[2][4][4];

    // ---- stage 1: sA = round(relu(rbf@Wemb + bemb)) ----
    fmma24_t<4>(sRbfA, sW, lane, arow0, col0, acc);
    {
        float2 bias[4];
#pragma unroll
        for (int nt = 0; nt < 4; nt++) bias[nt] = *(const float2*)&bemb[col0 + nt * 8 + cc * 2];
#pragma unroll
        for (int mt = 0; mt < 2; mt++)
#pragma unroll
            for (int h = 0; h < 2; h++) {
                int r = arow0 + mt * 16 + q + h * 8;
#pragma unroll
                for (int nt = 0; nt < 4; nt++) {
                    int c = col0 + nt * 8 + cc * 2;
                    sA[r * 260 + c]     = tf32r(fmaxf(acc[mt][nt][h * 2 + 0] + bias[nt].x, 0.f));
                    sA[r * 260 + c + 1] = tf32r(fmaxf(acc[mt][nt][h * 2 + 1] + bias[nt].y, 0.f));
                }
            }
    }
    __syncthreads();

    // ---- stage 2: sM = round(sA@Wpre2 + sM) ----
    mma_loop_t<4>(sA, 260, sW, sWu, g_Wpre2, 256, tid, lane, arow0, col0, acc);
#pragma unroll
    for (int mt = 0; mt < 2; mt++)
#pragma unroll
        for (int h = 0; h < 2; h++) {
            int r = arow0 + mt * 16 + q + h * 8;
#pragma unroll
            for (int nt = 0; nt < 4; nt++) {
                int c = col0 + nt * 8 + cc * 2;
                float* p = &sM[r * 260 + c];
                p[0] = tf32r(acc[mt][nt][h * 2 + 0] + p[0]);
                p[1] = tf32r(acc[mt][nt][h * 2 + 1] + p[1]);
            }
        }
    __syncthreads();

    // ---- stage 3: sA = round(silu(sM@Ws1 + bs1)) ----
    mma_loop_t<4>(sM, 260, sW, sWu, g_Ws1, 256, tid, lane, arow0, col0, acc);
    {
        float2 bias[4];
#pragma unroll
        for (int nt = 0; nt < 4; nt++) bias[nt] = *(const float2*)&bs1[col0 + nt * 8 + cc * 2];
#pragma unroll
        for (int mt = 0; mt < 2; mt++)
#pragma unroll
            for (int h = 0; h < 2; h++) {
                int r = arow0 + mt * 16 + q + h * 8;
#pragma unroll
                for (int nt = 0; nt < 4; nt++) {
                    int c = col0 + nt * 8 + cc * 2;
                    float m0 = acc[mt][nt][h * 2 + 0] + bias[nt].x;
                    float m1 = acc[mt][nt][h * 2 + 1] + bias[nt].y;
                    sA[r * 260 + c]     = tf32r(__fdividef(m0, 1.f + __expf(-m0)));
                    sA[r * 260 + c + 1] = tf32r(__fdividef(m1, 1.f + __expf(-m1)));
                }
            }
    }
    __syncthreads();

    // ---- stage 4: three 256-col chunks of Ws2, fused with f = rbf@Wlin ----
    for (int ch = 0; ch < 3; ch++) {
        mma_loop_t<4>(sA, 260, sW, sWu, g_Ws2 + ch * 256, 768, tid, lane, arow0, col0, acc);
        // Wlin chunk into sW rows 0..19, zero rows 20..23
#pragma unroll
        for (int j = 0; j < 5; j++) {
            int v = tid + j * 256, row = v >> 6, c4 = (v & 63) * 4;
            *(float4*)&sW[row * 264 + c4] = *(const float4*)&g_Wlin[row * 768 + ch * 256 + c4];
        }
        { int row = 20 + (tid >> 6), c4 = (tid & 63) * 4;
          *(float4*)&sW[row * 264 + c4] = make_float4(0.f, 0.f, 0.f, 0.f); }
        __syncthreads();
        float facc[2][4][4];
        fmma24_t<4>(sRbfA, sW, lane, arow0, col0, facc);
        float2 bias[4];
#pragma unroll
        for (int nt = 0; nt < 4; nt++)
            bias[nt] = *(const float2*)&bs2[ch * 256 + col0 + nt * 8 + cc * 2];

        if (ch == 0) {
            // g_state -> sM
#pragma unroll
            for (int mt = 0; mt < 2; mt++)
#pragma unroll
                for (int h = 0; h < 2; h++) {
                    int r = arow0 + mt * 16 + q + h * 8;
#pragma unroll
                    for (int nt = 0; nt < 4; nt++) {
                        int c = col0 + nt * 8 + cc * 2;
                        sM[r * 260 + c]     = (acc[mt][nt][h * 2 + 0] + bias[nt].x) * facc[mt][nt][h * 2 + 0];
                        sM[r * 260 + c + 1] = (acc[mt][nt][h * 2 + 1] + bias[nt].y) * facc[mt][nt][h * 2 + 1];
                    }
                }
            __syncthreads();
        } else if (ch == 1) {
            // g_edge: single-pass segmented mv scatter; full 32x256 ge scratch in sW
            // (sW = 8448 floats = 32 rows x 264 stride exactly; Wlin dead after fmma24)
            __syncthreads();  // all warps done reading Wlin from sW
#pragma unroll
            for (int mt = 0; mt < 2; mt++)
#pragma unroll
                for (int h = 0; h < 2; h++) {
                    int r = arow0 + mt * 16 + q + h * 8;
#pragma unroll
                    for (int nt = 0; nt < 4; nt++) {
                        int c = col0 + nt * 8 + cc * 2;
                        float g0 = (acc[mt][nt][h * 2 + 0] + bias[nt].x) * facc[mt][nt][h * 2 + 0];
                        float g1 = (acc[mt][nt][h * 2 + 1] + bias[nt].y) * facc[mt][nt][h * 2 + 1];
                        sW[r * 264 + c]     = g0;
                        sW[r * 264 + c + 1] = g1;
                    }
                }
            __syncthreads();
            {
                int c = tid;   // all 256 threads, one column each
                int dprev = sDst[0];
                float Sgs = 0.f, S0 = 0.f, S1 = 0.f, S2 = 0.f;
                for (int r = 0; r < TE; r++) {
                    int d = sDst[r];
                    if (d != dprev) {
                        float xv = x[(size_t)dprev * 256 + c];
                        float* vb = out_v + (size_t)dprev * 768 + c;
                        atomicAdd(vb,       fmaf(xv, Sgs, S0));
                        atomicAdd(vb + 256, fmaf(xv, Sgs, S1));
                        atomicAdd(vb + 512, fmaf(xv, Sgs, S2));
                        Sgs = S0 = S1 = S2 = 0.f;
                        dprev = d;
                    }
                    float gs = sM[r * 260 + c];
                    float ge = sW[r * 264 + c];
                    Sgs += gs;
                    S0 = fmaf(sEv[r * 3 + 0], ge, S0);
                    S1 = fmaf(sEv[r * 3 + 1], ge, S1);
                    S2 = fmaf(sEv[r * 3 + 2], ge, S2);
                }
                float xv = x[(size_t)dprev * 256 + c];
                float* vb = out_v + (size_t)dprev * 768 + c;
                atomicAdd(vb,       fmaf(xv, Sgs, S0));
                atomicAdd(vb + 256, fmaf(xv, Sgs, S1));
                atomicAdd(vb + 512, fmaf(xv, Sgs, S2));
            }
            __syncthreads();
        } else {
            // ms stats: write to sA (free after final GEMM), segmented scan + coalesced flush
#pragma unroll
            for (int mt = 0; mt < 2; mt++)
#pragma unroll
                for (int h = 0; h < 2; h++) {
                    int r = arow0 + mt * 16 + q + h * 8;
#pragma unroll
                    for (int nt = 0; nt < 4; nt++) {
                        int c = col0 + nt * 8 + cc * 2;
                        sA[r * 260 + c]     = (acc[mt][nt][h * 2 + 0] + bias[nt].x) * facc[mt][nt][h * 2 + 0];
                        sA[r * 260 + c + 1] = (acc[mt][nt][h * 2 + 1] + bias[nt].y) * facc[mt][nt][h * 2 + 1];
                    }
                }
            __syncthreads();
            {
                int c = tid;
                int dprev = sDst[0];
                float S = 0.f, SS = 0.f;
                float mn = __int_as_float(0x7f800000), mx = __int_as_float(0xff800000);
                for (int r = 0; r < TE; r++) {
                    int d = sDst[r];
                    if (d != dprev) {
                        int a = dprev * 256 + c;
                        atomicAdd(&g_sum[a], S);
                        atomicAdd(&g_sumsq[a], SS);
                        atomicMaxF(&g_maxb[a], mx);
                        atomicMinF(&g_minb[a], mn);
                        S = SS = 0.f;
                        mn = __int_as_float(0x7f800000);
                        mx = __int_as_float(0xff800000);
                        dprev = d;
                    }
                    float v = sA[r * 260 + c];
                    S += v;
                    SS = fmaf(v, v, SS);
                    mn = fminf(mn, v);
                    mx = fmaxf(mx, v);
                }
                int a = dprev * 256 + c;
                atomicAdd(&g_sum[a], S);
                atomicAdd(&g_sumsq[a], SS);
                atomicMaxF(&g_maxb[a], mx);
                atomicMinF(&g_minb[a], mn);
            }
        }
    }
}

// ---------------- aggs -> g_cat (rounded) ----------------
__global__ void agg_kernel() {
    int idx = blockIdx.x * 256 + threadIdx.x;
    if (idx >= NN * FF) return;
    int n = idx >> 8;
    int c = idx & 255;
    float deg  = g_deg[n];
    float degc = fmaxf(deg, 1.f);
    float mean = g_sum[idx] / degc;
    float msq  = g_sumsq[idx] / degc;
    float stdv = sqrtf(fmaxf(msq - mean * mean, 0.f) + 1e-5f);
    float mn = (deg > 0.f) ? g_minb[idx] : 0.f;
    float mx = (deg > 0.f) ? g_maxb[idx] : 0.f;
    float avg  = g_avglog;
    float logd = log1pf(deg);
    float s1 = logd / avg;
    float s2 = avg / log1pf(degc);
    float* base = g_cat + (size_t)n * 3328 + 256 + c;
    base[0 * FF]  = tf32r(mean);      base[1 * FF]  = tf32r(mn);
    base[2 * FF]  = tf32r(mx);        base[3 * FF]  = tf32r(stdv);
    base[4 * FF]  = tf32r(mean * s1); base[5 * FF]  = tf32r(mn * s1);
    base[6 * FF]  = tf32r(mx * s1);   base[7 * FF]  = tf32r(stdv * s1);
    base[8 * FF]  = tf32r(mean * s2); base[9 * FF]  = tf32r(mn * s2);
    base[10 * FF] = tf32r(mx * s2);   base[11 * FF] = tf32r(stdv * s2);
}

// ---------------- post GEMM: out_x = x + g_cat @ Wpost + bpost (tf32 mma) ----------------
__global__ __launch_bounds__(256) void gemm_post_kernel(const float* __restrict__ x,
                                                        const float* __restrict__ bpost,
                                                        float* __restrict__ out_x) {
    __shared__ float sW[2 * 16 * 264];
    __shared__ float sAt[2 * 64 * 20];
    uint32_t sWu = (uint32_t)__cvta_generic_to_shared(sW);
    uint32_t sAu = (uint32_t)__cvta_generic_to_shared(sAt);

    int tid = threadIdx.x, lane = tid & 31, w = tid >> 5;
    int arow0 = (w & 1) * 32, col0 = (w >> 1) * 64;
    int q = lane >> 2, cc = lane & 3;
    int n0 = blockIdx.x * 64;

    float acc[2][8][4];
#pragma unroll
    for (int mt = 0; mt < 2; mt++)
#pragma unroll
        for (int nt = 0; nt < 8; nt++)
#pragma unroll
            for (int z = 0; z < 4; z++) acc[mt][nt][z] = 0.f;

    int arow = tid >> 2, ac4 = (tid & 3) * 4;
    int asrc_n = min(n0 + arow, NN - 1);

    {
#pragma unroll
        for (int qq = 0; qq < 4; qq++) {
            int v = qq * 256 + tid, row = v >> 6, c4 = (v & 63) * 4;
            cp16(sWu + (uint32_t)((row * 264 + c4) * 4), g_Wpost + row * 256 + c4);
        }
        cp16(sAu + (uint32_t)((arow * 20 + ac4) * 4), g_cat + (size_t)asrc_n * 3328 + ac4);
        cp_commit();
    }
    const int KT = 3328 / 16;
    for (int t = 0; t < KT; t++) {
        if (t + 1 < KT) {
            int k0 = (t + 1) * 16;
            const float* wsrc = g_Wpost + (size_t)k0 * 256;
            uint32_t wb = sWu + (uint32_t)((((t + 1) & 1) * 16 * 264) * 4);
            uint32_t ab = sAu + (uint32_t)((((t + 1) & 1) * 64 * 20) * 4);
#pragma unroll
            for (int qq = 0; qq < 4; qq++) {
                int v = qq * 256 + tid, row = v >> 6, c4 = (v & 63) * 4;
                cp16(wb + (uint32_t)((row * 264 + c4) * 4), wsrc + row * 256 + c4);
            }
            cp16(ab + (uint32_t)((arow * 20 + ac4) * 4),
                 g_cat + (size_t)asrc_n * 3328 + k0 + ac4);
            cp_commit();
            cp_wait1();
        } else {
            cp_wait0();
        }
        __syncthreads();
        compute_k16_t<8>(sAt + (t & 1) * 64 * 20, 20, arow0, 0, sW + (t & 1) * 16 * 264,
                         lane, col0, acc);
        __syncthreads();
    }

#pragma unroll
    for (int mt = 0; mt < 2; mt++)
#pragma unroll
        for (int h = 0; h < 2; h++) {
            int r = arow0 + mt * 16 + q + h * 8;
            int n = n0 + r;
            if (n < NN) {
#pragma unroll
                for (int nt = 0; nt < 8; nt++) {
                    int c = col0 + nt * 8 + cc * 2;
                    float2 xv = *(const float2*)&x[(size_t)n * 256 + c];
                    float2 bb = *(const float2*)&bpost[c];
                    float2 o;
                    o.x = xv.x + acc[mt][nt][h * 2 + 0] + bb.x;
                    o.y = xv.y + acc[mt][nt][h * 2 + 1] + bb.y;
                    *(float2*)&out_x[(size_t)n * 256 + c] = o;
                }
            }
        }
}

// ---------------- launch ----------------
extern "C" void kernel_launch(void* const* d_in, const int* in_sizes, int n_in,
                              void* d_out, int out_size) {
    const float* x        = (const float*)d_in[0];
    const float* v        = (const float*)d_in[1];
    const float* edge_rbf = (const float*)d_in[2];
    const float* edge_vec = (const float*)d_in[3];
    const float* Wemb     = (const float*)d_in[4];
    const float* bemb     = (const float*)d_in[5];
    const float* Wpre     = (const float*)d_in[6];
    const float* bpre     = (const float*)d_in[7];
    const float* Ws1      = (const float*)d_in[8];
    const float* bs1      = (const float*)d_in[9];
    const float* Ws2      = (const float*)d_in[10];
    const float* bs2      = (const float*)d_in[11];
    const float* Wlin     = (const float*)d_in[12];
    const float* Wpost    = (const float*)d_in[13];
    const float* bpost    = (const float*)d_in[14];
    const int*   eidx     = (const int*)d_in[15];

    float* out_x = (float*)d_out;
    float* out_v = out_x + (size_t)NN * FF;

    cudaFuncSetAttribute(edge_kernel, cudaFuncAttributeMaxDynamicSharedMemorySize,
                         EDGE_SMEM_BYTES);

    cudaMemcpyAsync(out_v, v, (size_t)NN * 3 * FF * sizeof(float), cudaMemcpyDeviceToDevice);

    cvt_kernel<<<(3328 * FF + 255) / 256, 256>>>(Wemb, Wpre, Ws1, Ws2, Wlin, Wpost);
    init_kernel<<<(NN * FF + 255) / 256, 256>>>(x);
    hist_kernel<<<NCHUNK, 256>>>(eidx);
    scanA_kernel<<<(NN + 255) / 256, 256>>>();
    scanB_kernel<<<1, 256>>>();
    scatter_kernel<<<NCHUNK, 256>>>(eidx);
    gemm_pre_kernel<<<dim3((NN + 63) / 64, 2), 256>>>();
    edge_kernel<<<EE / TE, 256, EDGE_SMEM_BYTES>>>(x, edge_rbf, edge_vec,
                                                   bemb, bpre, bs1, bs2, out_v);
    agg_kernel<<<(NN * FF + 255) / 256, 256>>>();
    gemm_post_kernel<<<(NN + 63) / 64, 256>>>(x, bpost, out_x);
}

// round 17
// speedup vs baseline: 1.2196x; 1.0089x over previous
#include <cuda_runtime.h>
#include <math.h>
#include <stdint.h>

#define NN 10000
#define EE 160000
#define FF 256
#define RR 20
#define TE 32
#define CHUNK 2048
#define NCHUNK 79   // ceil(EE / CHUNK)

// ---------------- device scratch ----------------
__device__ float g_P0[NN * FF];
__device__ float g_P1[NN * FF];
__device__ float g_sum[NN * FF];
__device__ float g_sumsq[NN * FF];
__device__ float g_minb[NN * FF];
__device__ float g_maxb[NN * FF];
__device__ float g_deg[NN];
__device__ float g_avglog;
__device__ float g_cat[NN * 3328];
// sort scratch
__device__ int g_chunkCnt[NCHUNK * NN];
__device__ int g_binCnt[NN];
__device__ int g_binBase[NN];
__device__ int g_perm[EE];
__device__ int g_ssrc[EE];
__device__ int g_sdst[EE];
// tf32-rounded weight copies (row-major, unpacked)
__device__ float g_Wemb[RR * FF];
__device__ float g_Wpre0[FF * FF];
__device__ float g_Wpre1[FF * FF];
__device__ float g_Wpre2[FF * FF];
__device__ float g_Ws1[FF * FF];
__device__ float g_Ws2[FF * 3 * FF];
__device__ float g_Wlin[RR * 3 * FF];
__device__ float g_Wpost[3328 * FF];

// ---------------- helpers ----------------
__device__ __forceinline__ float tf32r(float x) {
    uint32_t u;
    asm("cvt.rna.tf32.f32 %0, %1;" : "=r"(u) : "f"(x));
    return __uint_as_float(u);
}
__device__ __forceinline__ uint32_t F2U(float f) { return __float_as_uint(f); }

__device__ __forceinline__ void mma8(float c[4], uint32_t a0, uint32_t a1, uint32_t a2,
                                     uint32_t a3, uint32_t b0, uint32_t b1) {
    asm volatile(
        "mma.sync.aligned.m16n8k8.row.col.f32.tf32.tf32.f32 "
        "{%0,%1,%2,%3},{%4,%5,%6,%7},{%8,%9},{%0,%1,%2,%3};"
        : "+f"(c[0]), "+f"(c[1]), "+f"(c[2]), "+f"(c[3])
        : "r"(a0), "r"(a1), "r"(a2), "r"(a3), "r"(b0), "r"(b1));
}

__device__ __forceinline__ void cp16(uint32_t saddr, const void* g) {
    asm volatile("cp.async.ca.shared.global [%0], [%1], 16;" :: "r"(saddr), "l"(g));
}
__device__ __forceinline__ void cp_commit() { asm volatile("cp.async.commit_group;"); }
__device__ __forceinline__ void cp_wait1()  { asm volatile("cp.async.wait_group 1;"); }
__device__ __forceinline__ void cp_wait0()  { asm volatile("cp.async.wait_group 0;"); }

__device__ __forceinline__ void atomicMaxF(float* p, float v) {
    if (v >= 0.f) atomicMax((int*)p, __float_as_int(v));
    else          atomicMin((unsigned int*)p, __float_as_uint(v));
}
__device__ __forceinline__ void atomicMinF(float* p, float v) {
    if (v >= 0.f) atomicMin((int*)p, __float_as_int(v));
    else          atomicMax((unsigned int*)p, __float_as_uint(v));
}

// ---------------- weight conversion + init (merged) ----------------
__global__ void cvt_init_kernel(const float* __restrict__ x,
                                const float* __restrict__ Wemb, const float* __restrict__ Wpre,
                                const float* __restrict__ Ws1, const float* __restrict__ Ws2,
                                const float* __restrict__ Wlin, const float* __restrict__ Wpost) {
    int i = blockIdx.x * 256 + threadIdx.x;
    if (i < RR * FF)     g_Wemb[i]  = tf32r(Wemb[i]);
    if (i < FF * FF) {
        g_Wpre0[i] = tf32r(Wpre[i]);
        g_Wpre1[i] = tf32r(Wpre[FF * FF + i]);
        g_Wpre2[i] = tf32r(Wpre[2 * FF * FF + i]);
        g_Ws1[i]   = tf32r(Ws1[i]);
    }
    if (i < FF * 3 * FF) g_Ws2[i]   = tf32r(Ws2[i]);
    if (i < RR * 3 * FF) g_Wlin[i]  = tf32r(Wlin[i]);
    if (i < 3328 * FF)   g_Wpost[i] = tf32r(Wpost[i]);
    if (i < NN * FF) {
        g_sum[i]   = 0.f;
        g_sumsq[i] = 0.f;
        g_minb[i]  = __int_as_float(0x7f800000);
        g_maxb[i]  = __int_as_float(0xff800000);
        int n = i >> 8, c = i & 255;
        g_cat[n * 3328 + c] = tf32r(x[i]);
    }
}

// ---------------- sort: per-chunk histogram (2048-edge chunks) ----------------
__global__ __launch_bounds__(256) void hist_kernel(const int* __restrict__ eidx) {
    __shared__ int shist[NN];
    int b = blockIdx.x, t = threadIdx.x;
    for (int i = t; i < NN; i += 256) shist[i] = 0;
    __syncthreads();
    int ebase = b * CHUNK;
#pragma unroll
    for (int j = 0; j < CHUNK / 256; j++) {
        int e = ebase + j * 256 + t;
        if (e < EE) atomicAdd(&shist[eidx[EE + e]], 1);
    }
    __syncthreads();
    for (int i = t; i < NN; i += 256) g_chunkCnt[b * NN + i] = shist[i];
}

// ---------------- sort: per-bin scan over chunks ----------------
__global__ void scanA_kernel() {
    int d = blockIdx.x * 256 + threadIdx.x;
    if (d >= NN) return;
    int run = 0;
    for (int b = 0; b < NCHUNK; b++) {
        int idx = b * NN + d;
        int t = g_chunkCnt[idx];
        g_chunkCnt[idx] = run;
        run += t;
    }
    g_binCnt[d] = run;
    g_deg[d] = (float)run;
}

// ---------------- sort: exclusive scan over bins + avg_log (single block) ----------------
__global__ void scanB_kernel() {
    __shared__ int sp[256];
    __shared__ float sf[256];
    int t = threadIdx.x;
    int lo = t * 40, hi = min(lo + 40, NN);
    int s = 0;
    float ls = 0.f;
    for (int i = lo; i < hi; i++) {
        int c = g_binCnt[i];
        s += c;
        ls += log1pf((float)c);
    }
    sp[t] = s;
    sf[t] = ls;
    __syncthreads();
    for (int off = 1; off < 256; off <<= 1) {
        int v = (t >= off) ? sp[t - off] : 0;
        __syncthreads();
        sp[t] += v;
        __syncthreads();
    }
    int base = (t > 0) ? sp[t - 1] : 0;
    for (int i = lo; i < hi; i++) {
        int c = g_binCnt[i];
        g_binBase[i] = base;
        base += c;
    }
    for (int off = 128; off > 0; off >>= 1) {
        if (t < off) sf[t] += sf[t + off];
        __syncthreads();
    }
    if (t == 0) g_avglog = sf[0] / (float)NN;
}

// ---------------- sort: scatter (atomic intra-chunk rank; grouping-only, unstable) ----------------
__global__ __launch_bounds__(256) void scatter_kernel(const int* __restrict__ eidx) {
    __shared__ int rc[NN];
    int b = blockIdx.x, t = threadIdx.x;
    for (int i = t; i < NN; i += 256) rc[i] = 0;
    __syncthreads();
    int ebase = b * CHUNK;
#pragma unroll
    for (int j = 0; j < CHUNK / 256; j++) {
        int e = ebase + j * 256 + t;
        if (e < EE) {
            int d = eidx[EE + e];
            int pos = g_binBase[d] + g_chunkCnt[b * NN + d] + atomicAdd(&rc[d], 1);
            g_perm[pos] = e;
            g_ssrc[pos] = eidx[e];
            g_sdst[pos] = d;
        }
    }
}

// ---------------- tf32 mma building blocks (templated N-tile; UNPACKED stride-264 B) ----------------
template <int NT>
__device__ __forceinline__ void compute_k16_t(const float* sA, int astr, int arow0, int k0,
                                              const float* sWb, int lane, int col0,
                                              float acc[2][NT][4]) {
    int q = lane >> 2, c = lane & 3;
#pragma unroll
    for (int ks = 0; ks < 16; ks += 8) {
        uint32_t a[2][4];
#pragma unroll
        for (int mt = 0; mt < 2; mt++) {
            const float* ap = sA + (arow0 + mt * 16 + q) * astr + k0 + ks + c;
            a[mt][0] = F2U(ap[0]);
            a[mt][2] = F2U(ap[4]);
            a[mt][1] = F2U(ap[8 * astr]);
            a[mt][3] = F2U(ap[8 * astr + 4]);
        }
#pragma unroll
        for (int nt = 0; nt < NT; nt++) {
            const float* bp = sWb + (ks + c) * 264 + col0 + nt * 8 + q;
            uint32_t b0 = F2U(bp[0]);
            uint32_t b1 = F2U(bp[4 * 264]);
            mma8(acc[0][nt], a[0][0], a[0][1], a[0][2], a[0][3], b0, b1);
            mma8(acc[1][nt], a[1][0], a[1][1], a[1][2], a[1][3], b0, b1);
        }
    }
}

template <int NT>
__device__ __forceinline__ void mma_loop_t(const float* sA, int astr, float* sW, uint32_t sWu,
                                           const float* __restrict__ Wg, int wst,
                                           int tid, int lane, int arow0, int col0,
                                           float acc[2][NT][4]) {
#pragma unroll
    for (int mt = 0; mt < 2; mt++)
#pragma unroll
        for (int nt = 0; nt < NT; nt++)
#pragma unroll
            for (int z = 0; z < 4; z++) acc[mt][nt][z] = 0.f;
    {
#pragma unroll
        for (int qq = 0; qq < 4; qq++) {
            int v = qq * 256 + tid, row = v >> 6, c4 = (v & 63) * 4;
            cp16(sWu + (uint32_t)((row * 264 + c4) * 4), Wg + row * wst + c4);
        }
        cp_commit();
    }
    for (int t = 0; t < 16; t++) {
        if (t + 1 < 16) {
            const float* src = Wg + (t + 1) * 16 * wst;
            uint32_t dbase = sWu + (uint32_t)((((t + 1) & 1) * 16 * 264) * 4);
#pragma unroll
            for (int qq = 0; qq < 4; qq++) {
                int v = qq * 256 + tid, row = v >> 6, c4 = (v & 63) * 4;
                cp16(dbase + (uint32_t)((row * 264 + c4) * 4), src + row * wst + c4);
            }
            cp_commit();
            cp_wait1();
        } else {
            cp_wait0();
        }
        __syncthreads();
        compute_k16_t<NT>(sA, astr, arow0, t * 16, sW + (t & 1) * 16 * 264, lane, col0, acc);
        __syncthreads();
    }
}

template <int NT>
__device__ __forceinline__ void fmma24_t(const float* sRbfA, const float* sW, int lane,
                                         int arow0, int col0, float facc[2][NT][4]) {
#pragma unroll
    for (int mt = 0; mt < 2; mt++)
#pragma unroll
        for (int nt = 0; nt < NT; nt++)
#pragma unroll
            for (int z = 0; z < 4; z++) facc[mt][nt][z] = 0.f;
    int q = lane >> 2, c = lane & 3;
#pragma unroll
    for (int ks = 0; ks < 24; ks += 8) {
        uint32_t a[2][4];
#pragma unroll
        for (int mt = 0; mt < 2; mt++) {
            const float* ap = sRbfA + (arow0 + mt * 16 + q) * 28 + ks + c;
            a[mt][0] = F2U(ap[0]);
            a[mt][2] = F2U(ap[4]);
            a[mt][1] = F2U(ap[8 * 28]);
            a[mt][3] = F2U(ap[8 * 28 + 4]);
        }
#pragma unroll
        for (int nt = 0; nt < NT; nt++) {
            const float* bp = sW + (ks + c) * 264 + col0 + nt * 8 + q;
            uint32_t b0 = F2U(bp[0]);
            uint32_t b1 = F2U(bp[4 * 264]);
            mma8(facc[0][nt], a[0][0], a[0][1], a[0][2], a[0][3], b0, b1);
            mma8(facc[1][nt], a[1][0], a[1][1], a[1][2], a[1][3], b0, b1);
        }
    }
}

// ---------------- node precompute P0/P1 (tf32 mma; A streamed from g_cat cols 0..255) ----------------
__global__ __launch_bounds__(256) void gemm_pre_kernel() {
    __shared__ float sW[2 * 16 * 264];
    __shared__ float sAt[2 * 64 * 20];
    uint32_t sWu = (uint32_t)__cvta_generic_to_shared(sW);
    uint32_t sAu = (uint32_t)__cvta_generic_to_shared(sAt);

    const float* Wg = blockIdx.y ? g_Wpre1 : g_Wpre0;
    float* P = blockIdx.y ? g_P1 : g_P0;

    int tid = threadIdx.x, lane = tid & 31, w = tid >> 5;
    int arow0 = (w & 1) * 32, col0 = (w >> 1) * 64;
    int q = lane >> 2, cc = lane & 3;
    int n0 = blockIdx.x * 64;

    float acc[2][8][4];
#pragma unroll
    for (int mt = 0; mt < 2; mt++)
#pragma unroll
        for (int nt = 0; nt < 8; nt++)
#pragma unroll
            for (int z = 0; z < 4; z++) acc[mt][nt][z] = 0.f;

    int arow = tid >> 2, ac4 = (tid & 3) * 4;
    int asrc_n = min(n0 + arow, NN - 1);

    {
#pragma unroll
        for (int qq = 0; qq < 4; qq++) {
            int v = qq * 256 + tid, row = v >> 6, c4 = (v & 63) * 4;
            cp16(sWu + (uint32_t)((row * 264 + c4) * 4), Wg + row * 256 + c4);
        }
        cp16(sAu + (uint32_t)((arow * 20 + ac4) * 4), g_cat + (size_t)asrc_n * 3328 + ac4);
        cp_commit();
    }
    const int KT = 16;
    for (int t = 0; t < KT; t++) {
        if (t + 1 < KT) {
            int k0 = (t + 1) * 16;
            const float* wsrc = Wg + (size_t)k0 * 256;
            uint32_t wb = sWu + (uint32_t)((((t + 1) & 1) * 16 * 264) * 4);
            uint32_t ab = sAu + (uint32_t)((((t + 1) & 1) * 64 * 20) * 4);
#pragma unroll
            for (int qq = 0; qq < 4; qq++) {
                int v = qq * 256 + tid, row = v >> 6, c4 = (v & 63) * 4;
                cp16(wb + (uint32_t)((row * 264 + c4) * 4), wsrc + row * 256 + c4);
            }
            cp16(ab + (uint32_t)((arow * 20 + ac4) * 4),
                 g_cat + (size_t)asrc_n * 3328 + k0 + ac4);
            cp_commit();
            cp_wait1();
        } else {
            cp_wait0();
        }
        __syncthreads();
        compute_k16_t<8>(sAt + (t & 1) * 64 * 20, 20, arow0, 0, sW + (t & 1) * 16 * 264,
                         lane, col0, acc);
        __syncthreads();
    }

#pragma unroll
    for (int mt = 0; mt < 2; mt++)
#pragma unroll
        for (int h = 0; h < 2; h++) {
            int r = arow0 + mt * 16 + q + h * 8;
            int n = n0 + r;
            if (n < NN) {
#pragma unroll
                for (int nt = 0; nt < 8; nt++) {
                    int c = col0 + nt * 8 + cc * 2;
                    float2 o;
                    o.x = acc[mt][nt][h * 2 + 0];
                    o.y = acc[mt][nt][h * 2 + 1];
                    *(float2*)&P[(size_t)n * 256 + c] = o;
                }
            }
        }
}

// ---------------- fused edge kernel (256 threads; 32 edges/CTA; 2 CTAs/SM) ----------------
// smem floats: sA 32x260 | sM 32x260 | sW 2x16x264 | sRbfA 32x28 | sEv 96 | src/dst/perm 96 ints
#define EDGE_SMEM_FLOATS (8320 + 8320 + 8448 + 896 + 96 + 96)
#define EDGE_SMEM_BYTES (EDGE_SMEM_FLOATS * 4)

__global__ __launch_bounds__(256, 2) void edge_kernel(
    const float* __restrict__ x, const float* __restrict__ edge_rbf,
    const float* __restrict__ edge_vec,
    const float* __restrict__ bemb, const float* __restrict__ bpre,
    const float* __restrict__ bs1, const float* __restrict__ bs2,
    float* __restrict__ out_v) {
    extern __shared__ float sm[];
    float* sA    = sm;
    float* sM    = sm + 8320;
    float* sW    = sm + 16640;
    float* sRbfA = sm + 25088;
    float* sEv   = sm + 25984;
    int* sSrc  = (int*)(sm + 26080);
    int* sDst  = sSrc + 32;
    int* sPerm = sDst + 32;
    uint32_t sWu = (uint32_t)__cvta_generic_to_shared(sW);

    int tid = threadIdx.x, lane = tid & 31, w = tid >> 5;
    const int arow0 = 0;
    int col0 = w * 32;                    // warp tile 32x32
    int q = lane >> 2, cc = lane & 3;
    int e0 = blockIdx.x * TE;

    if (tid < TE) {
        sSrc[tid]  = g_ssrc[e0 + tid];
        sDst[tid]  = g_sdst[e0 + tid];
        sPerm[tid] = g_perm[e0 + tid];
    }
    __syncthreads();

    // rbf gather (via perm), tf32-rounded, padded to 24 cols (stride 28): 640 elems
#pragma unroll
    for (int j = 0; j < 3; j++) {
        int i = tid + j * 256;
        if (i < TE * RR) {
            int e = i / 20, k = i - e * 20;
            sRbfA[e * 28 + k] = tf32r(edge_rbf[(size_t)sPerm[e] * RR + k]);
        }
    }
    if (tid < 128) { int e = tid >> 2, k = 20 + (tid & 3); sRbfA[e * 28 + k] = 0.f; }
    if (tid < 96) {
        int e = tid / 3, comp = tid - e * 3;
        sEv[tid] = edge_vec[(size_t)sPerm[e] * 3 + comp];
    }
    // Wemb -> sW rows 0..19, zero rows 20..23
#pragma unroll
    for (int j = 0; j < 5; j++) {
        int v = tid + j * 256, row = v >> 6, c4 = (v & 63) * 4;
        *(float4*)&sW[row * 264 + c4] = *(const float4*)&g_Wemb[row * 256 + c4];
    }
    { int row = 20 + (tid >> 6), c4 = (tid & 63) * 4;
      *(float4*)&sW[row * 264 + c4] = make_float4(0.f, 0.f, 0.f, 0.f); }
    __syncthreads();

    // prefill sM = P0[src] + P1[dst] + bpre (2048 float4s)
#pragma unroll
    for (int j = 0; j < 8; j++) {
        int f = (tid + j * 256) * 4;
        int r = f >> 8, c = f & 255;
        int s = sSrc[r], d = sDst[r];
        float4 p0 = *(const float4*)&g_P0[s * 256 + c];
        float4 p1 = *(const float4*)&g_P1[d * 256 + c];
        float4 bb = *(const float4*)&bpre[c];
        *(float4*)&sM[r * 260 + c] =
            make_float4(p0.x + p1.x + bb.x, p0.y + p1.y + bb.y,
                        p0.z + p1.z + bb.z, p0.w + p1.w + bb.w);
    }

    float acc[2][4][4];

    // ---- stage 1: sA = round(relu(rbf@Wemb + bemb)) ----
    fmma24_t<4>(sRbfA, sW, lane, arow0, col0, acc);
    {
        float2 bias[4];
#pragma unroll
        for (int nt = 0; nt < 4; nt++) bias[nt] = *(const float2*)&bemb[col0 + nt * 8 + cc * 2];
#pragma unroll
        for (int mt = 0; mt < 2; mt++)
#pragma unroll
            for (int h = 0; h < 2; h++) {
                int r = arow0 + mt * 16 + q + h * 8;
#pragma unroll
                for (int nt = 0; nt < 4; nt++) {
                    int c = col0 + nt * 8 + cc * 2;
                    sA[r * 260 + c]     = tf32r(fmaxf(acc[mt][nt][h * 2 + 0] + bias[nt].x, 0.f));
                    sA[r * 260 + c + 1] = tf32r(fmaxf(acc[mt][nt][h * 2 + 1] + bias[nt].y, 0.f));
                }
            }
    }
    __syncthreads();

    // ---- stage 2: sM = round(sA@Wpre2 + sM) ----
    mma_loop_t<4>(sA, 260, sW, sWu, g_Wpre2, 256, tid, lane, arow0, col0, acc);
#pragma unroll
    for (int mt = 0; mt < 2; mt++)
#pragma unroll
        for (int h = 0; h < 2; h++) {
            int r = arow0 + mt * 16 + q + h * 8;
#pragma unroll
            for (int nt = 0; nt < 4; nt++) {
                int c = col0 + nt * 8 + cc * 2;
                float* p = &sM[r * 260 + c];
                p[0] = tf32r(acc[mt][nt][h * 2 + 0] + p[0]);
                p[1] = tf32r(acc[mt][nt][h * 2 + 1] + p[1]);
            }
        }
    __syncthreads();

    // ---- stage 3: sA = round(silu(sM@Ws1 + bs1)) ----
    mma_loop_t<4>(sM, 260, sW, sWu, g_Ws1, 256, tid, lane, arow0, col0, acc);
    {
        float2 bias[4];
#pragma unroll
        for (int nt = 0; nt < 4; nt++) bias[nt] = *(const float2*)&bs1[col0 + nt * 8 + cc * 2];
#pragma unroll
        for (int mt = 0; mt < 2; mt++)
#pragma unroll
            for (int h = 0; h < 2; h++) {
                int r = arow0 + mt * 16 + q + h * 8;
#pragma unroll
                for (int nt = 0; nt < 4; nt++) {
                    int c = col0 + nt * 8 + cc * 2;
                    float m0 = acc[mt][nt][h * 2 + 0] + bias[nt].x;
                    float m1 = acc[mt][nt][h * 2 + 1] + bias[nt].y;
                    sA[r * 260 + c]     = tf32r(__fdividef(m0, 1.f + __expf(-m0)));
                    sA[r * 260 + c + 1] = tf32r(__fdividef(m1, 1.f + __expf(-m1)));
                }
            }
    }
    __syncthreads();

    // ---- stage 4: three 256-col chunks of Ws2, fused with f = rbf@Wlin ----
    for (int ch = 0; ch < 3; ch++) {
        mma_loop_t<4>(sA, 260, sW, sWu, g_Ws2 + ch * 256, 768, tid, lane, arow0, col0, acc);
        // Wlin chunk into sW rows 0..19, zero rows 20..23
#pragma unroll
        for (int j = 0; j < 5; j++) {
            int v = tid + j * 256, row = v >> 6, c4 = (v & 63) * 4;
            *(float4*)&sW[row * 264 + c4] = *(const float4*)&g_Wlin[row * 768 + ch * 256 + c4];
        }
        { int row = 20 + (tid >> 6), c4 = (tid & 63) * 4;
          *(float4*)&sW[row * 264 + c4] = make_float4(0.f, 0.f, 0.f, 0.f); }
        __syncthreads();
        float facc[2][4][4];
        fmma24_t<4>(sRbfA, sW, lane, arow0, col0, facc);
        float2 bias[4];
#pragma unroll
        for (int nt = 0; nt < 4; nt++)
            bias[nt] = *(const float2*)&bs2[ch * 256 + col0 + nt * 8 + cc * 2];

        if (ch == 0) {
            // g_state -> sM
#pragma unroll
            for (int mt = 0; mt < 2; mt++)
#pragma unroll
                for (int h = 0; h < 2; h++) {
                    int r = arow0 + mt * 16 + q + h * 8;
#pragma unroll
                    for (int nt = 0; nt < 4; nt++) {
                        int c = col0 + nt * 8 + cc * 2;
                        sM[r * 260 + c]     = (acc[mt][nt][h * 2 + 0] + bias[nt].x) * facc[mt][nt][h * 2 + 0];
                        sM[r * 260 + c + 1] = (acc[mt][nt][h * 2 + 1] + bias[nt].y) * facc[mt][nt][h * 2 + 1];
                    }
                }
            __syncthreads();
        } else if (ch == 1) {
            // g_edge: single-pass segmented mv scatter; full 32x256 ge scratch in sW
            __syncthreads();  // all warps done reading Wlin from sW
#pragma unroll
            for (int mt = 0; mt < 2; mt++)
#pragma unroll
                for (int h = 0; h < 2; h++) {
                    int r = arow0 + mt * 16 + q + h * 8;
#pragma unroll
                    for (int nt = 0; nt < 4; nt++) {
                        int c = col0 + nt * 8 + cc * 2;
                        float g0 = (acc[mt][nt][h * 2 + 0] + bias[nt].x) * facc[mt][nt][h * 2 + 0];
                        float g1 = (acc[mt][nt][h * 2 + 1] + bias[nt].y) * facc[mt][nt][h * 2 + 1];
                        sW[r * 264 + c]     = g0;
                        sW[r * 264 + c + 1] = g1;
                    }
                }
            __syncthreads();
            {
                int c = tid;
                int dprev = sDst[0];
                float Sgs = 0.f, S0 = 0.f, S1 = 0.f, S2 = 0.f;
                for (int r = 0; r < TE; r++) {
                    int d = sDst[r];
                    if (d != dprev) {
                        float xv = x[(size_t)dprev * 256 + c];
                        float* vb = out_v + (size_t)dprev * 768 + c;
                        atomicAdd(vb,       fmaf(xv, Sgs, S0));
                        atomicAdd(vb + 256, fmaf(xv, Sgs, S1));
                        atomicAdd(vb + 512, fmaf(xv, Sgs, S2));
                        Sgs = S0 = S1 = S2 = 0.f;
                        dprev = d;
                    }
                    float gs = sM[r * 260 + c];
                    float ge = sW[r * 264 + c];
                    Sgs += gs;
                    S0 = fmaf(sEv[r * 3 + 0], ge, S0);
                    S1 = fmaf(sEv[r * 3 + 1], ge, S1);
                    S2 = fmaf(sEv[r * 3 + 2], ge, S2);
                }
                float xv = x[(size_t)dprev * 256 + c];
                float* vb = out_v + (size_t)dprev * 768 + c;
                atomicAdd(vb,       fmaf(xv, Sgs, S0));
                atomicAdd(vb + 256, fmaf(xv, Sgs, S1));
                atomicAdd(vb + 512, fmaf(xv, Sgs, S2));
            }
            __syncthreads();
        } else {
            // ms stats: write to sA (free after final GEMM), segmented scan + coalesced flush
#pragma unroll
            for (int mt = 0; mt < 2; mt++)
#pragma unroll
                for (int h = 0; h < 2; h++) {
                    int r = arow0 + mt * 16 + q + h * 8;
#pragma unroll
                    for (int nt = 0; nt < 4; nt++) {
                        int c = col0 + nt * 8 + cc * 2;
                        sA[r * 260 + c]     = (acc[mt][nt][h * 2 + 0] + bias[nt].x) * facc[mt][nt][h * 2 + 0];
                        sA[r * 260 + c + 1] = (acc[mt][nt][h * 2 + 1] + bias[nt].y) * facc[mt][nt][h * 2 + 1];
                    }
                }
            __syncthreads();
            {
                int c = tid;
                int dprev = sDst[0];
                float S = 0.f, SS = 0.f;
                float mn = __int_as_float(0x7f800000), mx = __int_as_float(0xff800000);
                for (int r = 0; r < TE; r++) {
                    int d = sDst[r];
                    if (d != dprev) {
                        int a = dprev * 256 + c;
                        atomicAdd(&g_sum[a], S);
                        atomicAdd(&g_sumsq[a], SS);
                        atomicMaxF(&g_maxb[a], mx);
                        atomicMinF(&g_minb[a], mn);
                        S = SS = 0.f;
                        mn = __int_as_float(0x7f800000);
                        mx = __int_as_float(0xff800000);
                        dprev = d;
                    }
                    float v = sA[r * 260 + c];
                    S += v;
                    SS = fmaf(v, v, SS);
                    mn = fminf(mn, v);
                    mx = fmaxf(mx, v);
                }
                int a = dprev * 256 + c;
                atomicAdd(&g_sum[a], S);
                atomicAdd(&g_sumsq[a], SS);
                atomicMaxF(&g_maxb[a], mx);
                atomicMinF(&g_minb[a], mn);
            }
        }
    }
}

// ---------------- aggs -> g_cat (rounded) ----------------
__global__ void agg_kernel() {
    int idx = blockIdx.x * 256 + threadIdx.x;
    if (idx >= NN * FF) return;
    int n = idx >> 8;
    int c = idx & 255;
    float deg  = g_deg[n];
    float degc = fmaxf(deg, 1.f);
    float mean = g_sum[idx] / degc;
    float msq  = g_sumsq[idx] / degc;
    float stdv = sqrtf(fmaxf(msq - mean * mean, 0.f) + 1e-5f);
    float mn = (deg > 0.f) ? g_minb[idx] : 0.f;
    float mx = (deg > 0.f) ? g_maxb[idx] : 0.f;
    float avg  = g_avglog;
    float logd = log1pf(deg);
    float s1 = logd / avg;
    float s2 = avg / log1pf(degc);
    float* base = g_cat + (size_t)n * 3328 + 256 + c;
    base[0 * FF]  = tf32r(mean);      base[1 * FF]  = tf32r(mn);
    base[2 * FF]  = tf32r(mx);        base[3 * FF]  = tf32r(stdv);
    base[4 * FF]  = tf32r(mean * s1); base[5 * FF]  = tf32r(mn * s1);
    base[6 * FF]  = tf32r(mx * s1);   base[7 * FF]  = tf32r(stdv * s1);
    base[8 * FF]  = tf32r(mean * s2); base[9 * FF]  = tf32r(mn * s2);
    base[10 * FF] = tf32r(mx * s2);   base[11 * FF] = tf32r(stdv * s2);
}

// ---------------- post GEMM: out_x = x + g_cat @ Wpost + bpost (tf32 mma) ----------------
__global__ __launch_bounds__(256) void gemm_post_kernel(const float* __restrict__ x,
                                                        const float* __restrict__ bpost,
                                                        float* __restrict__ out_x) {
    __shared__ float sW[2 * 16 * 264];
    __shared__ float sAt[2 * 64 * 20];
    uint32_t sWu = (uint32_t)__cvta_generic_to_shared(sW);
    uint32_t sAu = (uint32_t)__cvta_generic_to_shared(sAt);

    int tid = threadIdx.x, lane = tid & 31, w = tid >> 5;
    int arow0 = (w & 1) * 32, col0 = (w >> 1) * 64;
    int q = lane >> 2, cc = lane & 3;
    int n0 = blockIdx.x * 64;

    float acc[2][8][4];
#pragma unroll
    for (int mt = 0; mt < 2; mt++)
#pragma unroll
        for (int nt = 0; nt < 8; nt++)
#pragma unroll
            for (int z = 0; z < 4; z++) acc[mt][nt][z] = 0.f;

    int arow = tid >> 2, ac4 = (tid & 3) * 4;
    int asrc_n = min(n0 + arow, NN - 1);

    {
#pragma unroll
        for (int qq = 0; qq < 4; qq++) {
            int v = qq * 256 + tid, row = v >> 6, c4 = (v & 63) * 4;
            cp16(sWu + (uint32_t)((row * 264 + c4) * 4), g_Wpost + row * 256 + c4);
        }
        cp16(sAu + (uint32_t)((arow * 20 + ac4) * 4), g_cat + (size_t)asrc_n * 3328 + ac4);
        cp_commit();
    }
    const int KT = 3328 / 16;
    for (int t = 0; t < KT; t++) {
        if (t + 1 < KT) {
            int k0 = (t + 1) * 16;
            const float* wsrc = g_Wpost + (size_t)k0 * 256;
            uint32_t wb = sWu + (uint32_t)((((t + 1) & 1) * 16 * 264) * 4);
            uint32_t ab = sAu + (uint32_t)((((t + 1) & 1) * 64 * 20) * 4);
#pragma unroll
            for (int qq = 0; qq < 4; qq++) {
                int v = qq * 256 + tid, row = v >> 6, c4 = (v & 63) * 4;
                cp16(wb + (uint32_t)((row * 264 + c4) * 4), wsrc + row * 256 + c4);
            }
            cp16(ab + (uint32_t)((arow * 20 + ac4) * 4),
                 g_cat + (size_t)asrc_n * 3328 + k0 + ac4);
            cp_commit();
            cp_wait1();
        } else {
            cp_wait0();
        }
        __syncthreads();
        compute_k16_t<8>(sAt + (t & 1) * 64 * 20, 20, arow0, 0, sW + (t & 1) * 16 * 264,
                         lane, col0, acc);
        __syncthreads();
    }

#pragma unroll
    for (int mt = 0; mt < 2; mt++)
#pragma unroll
        for (int h = 0; h < 2; h++) {
            int r = arow0 + mt * 16 + q + h * 8;
            int n = n0 + r;
            if (n < NN) {
#pragma unroll
                for (int nt = 0; nt < 8; nt++) {
                    int c = col0 + nt * 8 + cc * 2;
                    float2 xv = *(const float2*)&x[(size_t)n * 256 + c];
                    float2 bb = *(const float2*)&bpost[c];
                    float2 o;
                    o.x = xv.x + acc[mt][nt][h * 2 + 0] + bb.x;
                    o.y = xv.y + acc[mt][nt][h * 2 + 1] + bb.y;
                    *(float2*)&out_x[(size_t)n * 256 + c] = o;
                }
            }
        }
}

// ---------------- launch ----------------
extern "C" void kernel_launch(void* const* d_in, const int* in_sizes, int n_in,
                              void* d_out, int out_size) {
    const float* x        = (const float*)d_in[0];
    const float* v        = (const float*)d_in[1];
    const float* edge_rbf = (const float*)d_in[2];
    const float* edge_vec = (const float*)d_in[3];
    const float* Wemb     = (const float*)d_in[4];
    const float* bemb     = (const float*)d_in[5];
    const float* Wpre     = (const float*)d_in[6];
    const float* bpre     = (const float*)d_in[7];
    const float* Ws1      = (const float*)d_in[8];
    const float* bs1      = (const float*)d_in[9];
    const float* Ws2      = (const float*)d_in[10];
    const float* bs2      = (const float*)d_in[11];
    const float* Wlin     = (const float*)d_in[12];
    const float* Wpost    = (const float*)d_in[13];
    const float* bpost    = (const float*)d_in[14];
    const int*   eidx     = (const int*)d_in[15];

    float* out_x = (float*)d_out;
    float* out_v = out_x + (size_t)NN * FF;

    cudaFuncSetAttribute(edge_kernel, cudaFuncAttributeMaxDynamicSharedMemorySize,
                         EDGE_SMEM_BYTES);

    cudaMemcpyAsync(out_v, v, (size_t)NN * 3 * FF * sizeof(float), cudaMemcpyDeviceToDevice);

    cvt_init_kernel<<<(NN * FF + 255) / 256, 256>>>(x, Wemb, Wpre, Ws1, Ws2, Wlin, Wpost);
    hist_kernel<<<NCHUNK, 256>>>(eidx);
    scanA_kernel<<<(NN + 255) / 256, 256>>>();
    scanB_kernel<<<1, 256>>>();
    scatter_kernel<<<NCHUNK, 256>>>(eidx);
    gemm_pre_kernel<<<dim3((NN + 63) / 64, 2), 256>>>();
    edge_kernel<<<EE / TE, 256, EDGE_SMEM_BYTES>>>(x, edge_rbf, edge_vec,
                                                   bemb, bpre, bs1, bs2, out_v);
    agg_kernel<<<(NN * FF + 255) / 256, 256>>>();
    gemm_post_kernel<<<(NN + 63) / 64, 256>>>(x, bpost, out_x);
}